// round 1
// baseline (speedup 1.0000x reference)
#include <cuda_runtime.h>
#include <math.h>

#define H 128
#define DMSG 256
#define MAXE 480000
#define MAXN 20000

// ---- scratch (no allocations allowed) ----
__device__ float g_hmsg[(size_t)MAXE * H];   // unscaled h_message
__device__ float g_att[MAXE];                // per-edge attention numerator
__device__ float g_denom[MAXN];              // per-node attention denominator
__device__ float g_dh[(size_t)MAXN * H];     // aggregated messages

// ---------------------------------------------------------------------------
// zero init for accumulators
// ---------------------------------------------------------------------------
__global__ void zero_kernel(int N) {
    int i = blockIdx.x * blockDim.x + threadIdx.x;
    if (i < N * H) g_dh[i] = 0.f;
    if (i < N) g_denom[i] = 0.f;
}

// ---------------------------------------------------------------------------
// edge kernel: 64 edges/block, 256 threads
// ---------------------------------------------------------------------------
constexpr int TE = 64;
constexpr int MS = 260;   // message row stride (floats)
constexpr int HS = 132;   // hidden row stride
constexpr int EDGE_SMEM = (TE * MS + TE * HS + 64 * 128) * 4 + TE * 4;

// C[64][128] = act(A[64][K] @ W[K][128] + bias)
// thread (ty=t/16 -> rows ty*4..+4, tx=t%16 -> cols {tx*4+j, 64+tx*4+j})
template <int ACT, bool TOSMEM>
__device__ __forceinline__ void gemm_tile(
    const float* sA, int lda, int K,
    const float* __restrict__ W, const float* __restrict__ bias,
    float* s_ws, float* sC, int ldc,
    float* gC, int e0, int E)
{
    const int t = threadIdx.x;
    const int tx = t & 15, ty = t >> 4;
    float acc[4][8];
#pragma unroll
    for (int i = 0; i < 4; i++)
#pragma unroll
        for (int j = 0; j < 8; j++) acc[i][j] = 0.f;

    for (int k0 = 0; k0 < K; k0 += 64) {
        // stage 64x128 weight chunk (2048 float4, 8 per thread)
#pragma unroll
        for (int j = 0; j < 8; j++) {
            int idx = t + 256 * j;
            int row = idx >> 5;
            int c4  = idx & 31;
            float4 v = *reinterpret_cast<const float4*>(W + (size_t)(k0 + row) * 128 + c4 * 4);
            *reinterpret_cast<float4*>(s_ws + row * 128 + c4 * 4) = v;
        }
        __syncthreads();
#pragma unroll 16
        for (int kk = 0; kk < 64; kk++) {
            float a0 = sA[(ty * 4 + 0) * lda + k0 + kk];
            float a1 = sA[(ty * 4 + 1) * lda + k0 + kk];
            float a2 = sA[(ty * 4 + 2) * lda + k0 + kk];
            float a3 = sA[(ty * 4 + 3) * lda + k0 + kk];
            float4 wa = *reinterpret_cast<const float4*>(s_ws + kk * 128 + tx * 4);
            float4 wb = *reinterpret_cast<const float4*>(s_ws + kk * 128 + 64 + tx * 4);
            float av[4] = {a0, a1, a2, a3};
#pragma unroll
            for (int i = 0; i < 4; i++) {
                acc[i][0] += av[i] * wa.x;  acc[i][1] += av[i] * wa.y;
                acc[i][2] += av[i] * wa.z;  acc[i][3] += av[i] * wa.w;
                acc[i][4] += av[i] * wb.x;  acc[i][5] += av[i] * wb.y;
                acc[i][6] += av[i] * wb.z;  acc[i][7] += av[i] * wb.w;
            }
        }
        __syncthreads();
    }
    // epilogue
#pragma unroll
    for (int i = 0; i < 4; i++) {
        int r = ty * 4 + i;
#pragma unroll
        for (int j = 0; j < 8; j++) {
            int col = (j < 4) ? (tx * 4 + j) : (64 + tx * 4 + (j - 4));
            float v = acc[i][j] + bias[col];
            if (ACT) v = (v >= 0.f) ? v : 0.01f * v;
            if (TOSMEM) {
                sC[r * ldc + col] = v;
            } else {
                int e = e0 + r;
                if (e < E) gC[(size_t)e * H + col] = v;
            }
        }
    }
}

__global__ void __launch_bounds__(256)
edge_kernel(const float* __restrict__ hV, const float* __restrict__ hE,
            const int* __restrict__ eidx,
            const float* __restrict__ w1, const float* __restrict__ b1,
            const float* __restrict__ w2, const float* __restrict__ b2,
            const float* __restrict__ w3, const float* __restrict__ b3,
            const float* __restrict__ A, int E)
{
    extern __shared__ float sm[];
    float* s_msg = sm;                   // TE x MS
    float* s_h   = sm + TE * MS;         // TE x HS
    float* s_ws  = s_h + TE * HS;        // 64 x 128
    int*   s_dst = (int*)(s_ws + 64 * 128);

    const int t = threadIdx.x;
    const int e0 = blockIdx.x * TE;

    if (t < TE) {
        int e = e0 + t;
        s_dst[t] = (e < E) ? eidx[e] : 0;
    }
    __syncthreads();

    // load message tile: [64][256] = [hV[dst] | hE], 4096 float4
#pragma unroll
    for (int j = 0; j < 16; j++) {
        int idx = t + 256 * j;
        int r  = idx >> 6;
        int c4 = idx & 63;
        int e  = e0 + r;
        float4 v = make_float4(0.f, 0.f, 0.f, 0.f);
        if (e < E) {
            if (c4 < 32)
                v = *reinterpret_cast<const float4*>(hV + (size_t)s_dst[r] * H + c4 * 4);
            else
                v = *reinterpret_cast<const float4*>(hE + (size_t)e * H + (c4 - 32) * 4);
        }
        *reinterpret_cast<float4*>(s_msg + r * MS + c4 * 4) = v;
    }
    __syncthreads();

    // attention numerator: 4 threads per edge
    {
        int r = t >> 2, p = t & 3;
        float s = 0.f;
        const float* m = s_msg + r * MS + p * 64;
#pragma unroll 16
        for (int c = 0; c < 64; c++) s += m[c] * __ldg(A + p * 64 + c);
        s += __shfl_xor_sync(0xffffffffu, s, 1);
        s += __shfl_xor_sync(0xffffffffu, s, 2);
        if (p == 0) {
            int e = e0 + r;
            if (e < E) {
                float lr = (s >= 0.f) ? s : 0.01f * s;
                float sg = 1.f / (1.f + expf(-lr));
                float a  = expf(sg);
                g_att[e] = a;
                atomicAdd(&g_denom[s_dst[r]], a);
            }
        }
    }

    // 3-layer MLP
    gemm_tile<1, true >(s_msg, MS, 256, w1, b1, s_ws, s_h,   HS, nullptr, e0, E);
    gemm_tile<1, true >(s_h,   HS, 128, w2, b2, s_ws, s_msg, MS, nullptr, e0, E);
    gemm_tile<0, false>(s_msg, MS, 128, w3, b3, s_ws, nullptr, 0, g_hmsg, e0, E);
}

// ---------------------------------------------------------------------------
// scatter: one warp per edge, atomic accumulate into dh
// ---------------------------------------------------------------------------
__global__ void scatter_kernel(const int* __restrict__ eidx, int E) {
    int gwarp = (blockIdx.x * blockDim.x + threadIdx.x) >> 5;
    int lane  = threadIdx.x & 31;
    if (gwarp >= E) return;
    int e = gwarp;
    int d = eidx[e];
    float coef = g_att[e] / (g_denom[d] * 30.0f);
    float4 v = *reinterpret_cast<const float4*>(g_hmsg + (size_t)e * H + lane * 4);
    float* dst = g_dh + (size_t)d * H + lane * 4;
    atomicAdd(dst + 0, v.x * coef);
    atomicAdd(dst + 1, v.y * coef);
    atomicAdd(dst + 2, v.z * coef);
    atomicAdd(dst + 3, v.w * coef);
}

// ---------------------------------------------------------------------------
// node kernel: 32 nodes/block, 256 threads. LN1 -> FFN(128->512->128) -> LN2
// ---------------------------------------------------------------------------
constexpr int NT = 32;
constexpr int XS = 132;
constexpr int NODE_SMEM = (NT * XS * 2 + 64 * 128) * 4;

__device__ __forceinline__ void ln_rows(float* s, const float* __restrict__ gain,
                                        const float* __restrict__ bias) {
    int t = threadIdx.x;
    int r = t >> 3, p = t & 7;
    float sm = 0.f, sq = 0.f;
#pragma unroll
    for (int c = p; c < H; c += 8) {
        float v = s[r * XS + c];
        sm += v; sq += v * v;
    }
#pragma unroll
    for (int o = 1; o < 8; o <<= 1) {
        sm += __shfl_xor_sync(0xffffffffu, sm, o);
        sq += __shfl_xor_sync(0xffffffffu, sq, o);
    }
    float mu  = sm * (1.f / 128.f);
    float var = sq * (1.f / 128.f) - mu * mu;
    float rs  = rsqrtf(var + 1e-6f);
#pragma unroll
    for (int c = p; c < H; c += 8) {
        float v = s[r * XS + c];
        s[r * XS + c] = gain[c] * (v - mu) * rs + bias[c];
    }
}

__global__ void __launch_bounds__(256)
node_kernel(const float* __restrict__ hV,
            const float* __restrict__ wi, const float* __restrict__ bi,
            const float* __restrict__ wo, const float* __restrict__ bo,
            const float* __restrict__ g1, const float* __restrict__ be1,
            const float* __restrict__ g2, const float* __restrict__ be2,
            float* __restrict__ out, int N)
{
    extern __shared__ float sm[];
    float* s_x  = sm;                 // NT x XS : LN1(h_V + dh)
    float* s_t  = sm + NT * XS;       // NT x XS : hidden chunk / z
    float* s_ws = s_t + NT * XS;      // 64 x 128

    const int t = threadIdx.x;
    const int n0 = blockIdx.x * NT;

    // load x = hV + dh
#pragma unroll
    for (int j = 0; j < 16; j++) {
        int idx = t + 256 * j;
        int r = idx >> 7, c = idx & 127;
        int n = n0 + r;
        float v = 0.f;
        if (n < N) v = hV[(size_t)n * H + c] + g_dh[(size_t)n * H + c];
        s_x[r * XS + c] = v;
    }
    __syncthreads();
    ln_rows(s_x, g1, be1);
    __syncthreads();

    // FFN
    const int tx = t & 15, ty = t >> 4;  // rows ty*2,+1 ; cols {tx*4+j, 64+tx*4+j}
    float oacc[2][8];
#pragma unroll
    for (int i = 0; i < 2; i++)
#pragma unroll
        for (int j = 0; j < 8; j++) oacc[i][j] = 0.f;

    for (int ch = 0; ch < 4; ch++) {
        // GEMM A: s_t[32][128] = relu(s_x @ wi[:, ch*128:+128] + bi)
        float tacc[2][8];
#pragma unroll
        for (int i = 0; i < 2; i++)
#pragma unroll
            for (int j = 0; j < 8; j++) tacc[i][j] = 0.f;
        for (int k0 = 0; k0 < 128; k0 += 64) {
#pragma unroll
            for (int j = 0; j < 8; j++) {
                int idx = t + 256 * j;
                int row = idx >> 5, c4 = idx & 31;
                float4 v = *reinterpret_cast<const float4*>(
                    wi + (size_t)(k0 + row) * 512 + ch * 128 + c4 * 4);
                *reinterpret_cast<float4*>(s_ws + row * 128 + c4 * 4) = v;
            }
            __syncthreads();
#pragma unroll 16
            for (int kk = 0; kk < 64; kk++) {
                float a0 = s_x[(ty * 2 + 0) * XS + k0 + kk];
                float a1 = s_x[(ty * 2 + 1) * XS + k0 + kk];
                float4 wa = *reinterpret_cast<const float4*>(s_ws + kk * 128 + tx * 4);
                float4 wb = *reinterpret_cast<const float4*>(s_ws + kk * 128 + 64 + tx * 4);
                tacc[0][0] += a0 * wa.x; tacc[0][1] += a0 * wa.y; tacc[0][2] += a0 * wa.z; tacc[0][3] += a0 * wa.w;
                tacc[0][4] += a0 * wb.x; tacc[0][5] += a0 * wb.y; tacc[0][6] += a0 * wb.z; tacc[0][7] += a0 * wb.w;
                tacc[1][0] += a1 * wa.x; tacc[1][1] += a1 * wa.y; tacc[1][2] += a1 * wa.z; tacc[1][3] += a1 * wa.w;
                tacc[1][4] += a1 * wb.x; tacc[1][5] += a1 * wb.y; tacc[1][6] += a1 * wb.z; tacc[1][7] += a1 * wb.w;
            }
            __syncthreads();
        }
#pragma unroll
        for (int i = 0; i < 2; i++) {
            int r = ty * 2 + i;
#pragma unroll
            for (int j = 0; j < 8; j++) {
                int col = (j < 4) ? (tx * 4 + j) : (64 + tx * 4 + (j - 4));
                float v = tacc[i][j] + bi[ch * 128 + col];
                s_t[r * XS + col] = fmaxf(v, 0.f);
            }
        }
        // GEMM B: oacc += s_t @ wo[ch*128:+128, :]
        for (int k0 = 0; k0 < 128; k0 += 64) {
#pragma unroll
            for (int j = 0; j < 8; j++) {
                int idx = t + 256 * j;
                int row = idx >> 5, c4 = idx & 31;
                float4 v = *reinterpret_cast<const float4*>(
                    wo + (size_t)(ch * 128 + k0 + row) * 128 + c4 * 4);
                *reinterpret_cast<float4*>(s_ws + row * 128 + c4 * 4) = v;
            }
            __syncthreads();
#pragma unroll 16
            for (int kk = 0; kk < 64; kk++) {
                float a0 = s_t[(ty * 2 + 0) * XS + k0 + kk];
                float a1 = s_t[(ty * 2 + 1) * XS + k0 + kk];
                float4 wa = *reinterpret_cast<const float4*>(s_ws + kk * 128 + tx * 4);
                float4 wb = *reinterpret_cast<const float4*>(s_ws + kk * 128 + 64 + tx * 4);
                oacc[0][0] += a0 * wa.x; oacc[0][1] += a0 * wa.y; oacc[0][2] += a0 * wa.z; oacc[0][3] += a0 * wa.w;
                oacc[0][4] += a0 * wb.x; oacc[0][5] += a0 * wb.y; oacc[0][6] += a0 * wb.z; oacc[0][7] += a0 * wb.w;
                oacc[1][0] += a1 * wa.x; oacc[1][1] += a1 * wa.y; oacc[1][2] += a1 * wa.z; oacc[1][3] += a1 * wa.w;
                oacc[1][4] += a1 * wb.x; oacc[1][5] += a1 * wb.y; oacc[1][6] += a1 * wb.z; oacc[1][7] += a1 * wb.w;
            }
            __syncthreads();
        }
    }
    // z = s_x + FFN + bo  -> s_t
#pragma unroll
    for (int i = 0; i < 2; i++) {
        int r = ty * 2 + i;
#pragma unroll
        for (int j = 0; j < 8; j++) {
            int col = (j < 4) ? (tx * 4 + j) : (64 + tx * 4 + (j - 4));
            s_t[r * XS + col] = s_x[r * XS + col] + oacc[i][j] + bo[col];
        }
    }
    __syncthreads();
    ln_rows(s_t, g2, be2);
    __syncthreads();

    // write out
#pragma unroll
    for (int j = 0; j < 16; j++) {
        int idx = t + 256 * j;
        int r = idx >> 7, c = idx & 127;
        int n = n0 + r;
        if (n < N) out[(size_t)n * H + c] = s_t[r * XS + c];
    }
}

// ---------------------------------------------------------------------------
extern "C" void kernel_launch(void* const* d_in, const int* in_sizes, int n_in,
                              void* d_out, int out_size)
{
    const float* hV  = (const float*)d_in[0];
    const float* hE  = (const float*)d_in[1];
    const float* w1  = (const float*)d_in[2];
    const float* b1  = (const float*)d_in[3];
    const float* w2  = (const float*)d_in[4];
    const float* b2  = (const float*)d_in[5];
    const float* w3  = (const float*)d_in[6];
    const float* b3  = (const float*)d_in[7];
    const float* A   = (const float*)d_in[8];
    const float* wi  = (const float*)d_in[9];
    const float* bi  = (const float*)d_in[10];
    const float* wo  = (const float*)d_in[11];
    const float* bo  = (const float*)d_in[12];
    const float* g1  = (const float*)d_in[13];
    const float* be1 = (const float*)d_in[14];
    const float* g2  = (const float*)d_in[15];
    const float* be2 = (const float*)d_in[16];
    const int*   eix = (const int*)d_in[17];

    int N = in_sizes[0] / H;
    int E = in_sizes[17] / 2;
    float* out = (float*)d_out;

    cudaFuncSetAttribute(edge_kernel, cudaFuncAttributeMaxDynamicSharedMemorySize, EDGE_SMEM);
    cudaFuncSetAttribute(node_kernel, cudaFuncAttributeMaxDynamicSharedMemorySize, NODE_SMEM);

    zero_kernel<<<(N * H + 255) / 256, 256>>>(N);
    edge_kernel<<<(E + TE - 1) / TE, 256, EDGE_SMEM>>>(hV, hE, eix, w1, b1, w2, b2, w3, b3, A, E);
    scatter_kernel<<<((size_t)E * 32 + 255) / 256, 256>>>(eix, E);
    node_kernel<<<(N + NT - 1) / NT, 256, NODE_SMEM>>>(hV, wi, bi, wo, bo, g1, be1, g2, be2, out, N);
}

// round 2
// speedup vs baseline: 2.3012x; 2.3012x over previous
#include <cuda_runtime.h>
#include <math.h>
#include <stdint.h>

#define H 128
#define MAXE 480000
#define MAXN 20000

// ---- scratch (no allocations allowed) ----
__device__ float g_att[MAXE];                // per-edge attention numerator
__device__ float g_denom[MAXN];              // per-node attention denominator
__device__ float g_p[MAXN];                  // h_V . A[:128] per node
__device__ float g_dh[(size_t)MAXN * H];     // aggregated messages

// ---------------------------------------------------------------------------
__global__ void zero_kernel(int N) {
    int i = blockIdx.x * blockDim.x + threadIdx.x;
    if (i < N * H) g_dh[i] = 0.f;
    if (i < N) g_denom[i] = 0.f;
}

// ---------------------------------------------------------------------------
// att_node: p[n] = dot(h_V[n], A[0:128]).  One warp per node.
// ---------------------------------------------------------------------------
__global__ void att_node_kernel(const float* __restrict__ hV,
                                const float* __restrict__ A, int N) {
    int w = (blockIdx.x * blockDim.x + threadIdx.x) >> 5;
    int lane = threadIdx.x & 31;
    if (w >= N) return;
    float4 v = *reinterpret_cast<const float4*>(hV + (size_t)w * H + lane * 4);
    float4 a = *reinterpret_cast<const float4*>(A + lane * 4);
    float s = v.x * a.x + v.y * a.y + v.z * a.z + v.w * a.w;
#pragma unroll
    for (int o = 16; o > 0; o >>= 1) s += __shfl_xor_sync(0xffffffffu, s, o);
    if (lane == 0) g_p[w] = s;
}

// ---------------------------------------------------------------------------
// att_edge: att[e] = exp(sigmoid(leaky(p[dst] + hE[e].A[128:]))); denom atomic.
// ---------------------------------------------------------------------------
__global__ void att_edge_kernel(const float* __restrict__ hE,
                                const float* __restrict__ A,
                                const int* __restrict__ eidx, int E) {
    int w = (blockIdx.x * blockDim.x + threadIdx.x) >> 5;
    int lane = threadIdx.x & 31;
    if (w >= E) return;
    float4 v = *reinterpret_cast<const float4*>(hE + (size_t)w * H + lane * 4);
    float4 a = *reinterpret_cast<const float4*>(A + 128 + lane * 4);
    float s = v.x * a.x + v.y * a.y + v.z * a.z + v.w * a.w;
#pragma unroll
    for (int o = 16; o > 0; o >>= 1) s += __shfl_xor_sync(0xffffffffu, s, o);
    if (lane == 0) {
        int d = eidx[w];
        s += g_p[d];
        float lr = (s >= 0.f) ? s : 0.01f * s;
        float sg = 1.f / (1.f + expf(-lr));
        float att = expf(sg);
        g_att[w] = att;
        atomicAdd(&g_denom[d], att);
    }
}

// ---------------------------------------------------------------------------
// tf32 helpers
// ---------------------------------------------------------------------------
__device__ __forceinline__ float to_tf32(float x) {
    uint32_t u;
    asm("cvt.rna.tf32.f32 %0, %1;" : "=r"(u) : "f"(x));
    return __uint_as_float(u);
}

__device__ __forceinline__ void mma_tf32(float d[4], const uint32_t a[4],
                                         uint32_t b0, uint32_t b1) {
    asm volatile(
        "mma.sync.aligned.m16n8k8.row.col.f32.tf32.tf32.f32 "
        "{%0,%1,%2,%3}, {%4,%5,%6,%7}, {%8,%9}, {%0,%1,%2,%3};"
        : "+f"(d[0]), "+f"(d[1]), "+f"(d[2]), "+f"(d[3])
        : "r"(a[0]), "r"(a[1]), "r"(a[2]), "r"(a[3]), "r"(b0), "r"(b1));
}

// ---------------------------------------------------------------------------
// edge MMA kernel: 128 edges/CTA, 256 threads (8 warps, 4x2 grid of 32x64)
// ---------------------------------------------------------------------------
constexpr int AS = 68;    // A-chunk stride (bank = 4*row'+col', conflict-free)
constexpr int WS = 136;   // W-chunk stride (bank = 8*k'+n', conflict-free)
constexpr int HS2 = 132;  // hidden stride  (bank = 4*row'+col', conflict-free)

constexpr int SM_AC   = 0;                       // 128 x 68
constexpr int SM_W    = SM_AC + 128 * AS;        // 64 x 136
constexpr int SM_H1   = SM_W + 64 * WS;          // 128 x 132
constexpr int SM_H2   = SM_H1 + 128 * HS2;       // 128 x 132
constexpr int SM_COEF = SM_H2 + 128 * HS2;       // 128
constexpr int SM_DST  = SM_COEF + 128;           // 128 (int)
constexpr int EDGE_SMEM = (SM_DST + 128) * 4;

// stage 64x128 weight chunk into [k][136] with tf32 rounding
__device__ __forceinline__ void stage_w(float* s_w, const float* __restrict__ Wg) {
    int t = threadIdx.x;
#pragma unroll
    for (int j = 0; j < 8; j++) {
        int idx = t + 256 * j;          // 2048 float4
        int k = idx >> 5, c4 = idx & 31;
        float4 v = *reinterpret_cast<const float4*>(Wg + (size_t)k * 128 + c4 * 4);
        v.x = to_tf32(v.x); v.y = to_tf32(v.y); v.z = to_tf32(v.z); v.w = to_tf32(v.w);
        *reinterpret_cast<float4*>(s_w + k * WS + c4 * 4) = v;
    }
}

// stage 128x64 message chunk (cols kc*64 .. +63) into [r][68]
__device__ __forceinline__ void stage_msg(float* s_ac, const float* __restrict__ hV,
                                          const float* __restrict__ hE,
                                          const int* s_dst, int e0, int kc, int E) {
    int t = threadIdx.x;
#pragma unroll
    for (int j = 0; j < 8; j++) {
        int idx = t + 256 * j;          // 2048 float4
        int r = idx >> 4, c4 = idx & 15;
        int col0 = kc * 64 + c4 * 4;
        float4 v = make_float4(0.f, 0.f, 0.f, 0.f);
        if (e0 + r < E) {
            if (col0 < 128)
                v = *reinterpret_cast<const float4*>(hV + (size_t)s_dst[r] * H + col0);
            else
                v = *reinterpret_cast<const float4*>(hE + (size_t)(e0 + r) * H + col0 - 128);
        }
        v.x = to_tf32(v.x); v.y = to_tf32(v.y); v.z = to_tf32(v.z); v.w = to_tf32(v.w);
        *reinterpret_cast<float4*>(s_ac + r * AS + c4 * 4) = v;
    }
}

// one 64-wide K chunk of warp-level MMA: 8 k-steps, 2x8 mma tiles
__device__ __forceinline__ void warp_gemm_chunk(const float* sA, int lda,
                                                const float* sW,
                                                float acc[2][8][4],
                                                int m0, int n0, int lx, int ly) {
#pragma unroll
    for (int kk = 0; kk < 8; kk++) {
        int kb = kk * 8;
        uint32_t a[2][4];
#pragma unroll
        for (int i = 0; i < 2; i++) {
            const float* ap = sA + (m0 + 16 * i + ly) * lda + kb + lx;
            a[i][0] = __float_as_uint(ap[0]);
            a[i][1] = __float_as_uint(ap[8 * lda]);
            a[i][2] = __float_as_uint(ap[4]);
            a[i][3] = __float_as_uint(ap[8 * lda + 4]);
        }
#pragma unroll
        for (int j = 0; j < 8; j++) {
            const float* bp = sW + (kb + lx) * WS + n0 + 8 * j + ly;
            uint32_t b0 = __float_as_uint(bp[0]);
            uint32_t b1 = __float_as_uint(bp[4 * WS]);
#pragma unroll
            for (int i = 0; i < 2; i++) mma_tf32(acc[i][j], a[i], b0, b1);
        }
    }
}

// epilogue: leaky-relu + bias -> smem (tf32-rounded for next layer's A)
__device__ __forceinline__ void epi_act(float acc[2][8][4], float* sH,
                                        const float* __restrict__ bias,
                                        int m0, int n0, int lx, int ly) {
#pragma unroll
    for (int j = 0; j < 8; j++) {
        int col = n0 + 8 * j + 2 * lx;
        float bb0 = __ldg(bias + col), bb1 = __ldg(bias + col + 1);
#pragma unroll
        for (int i = 0; i < 2; i++) {
            int r0 = m0 + 16 * i + ly;
            float v0 = acc[i][j][0] + bb0; v0 = (v0 >= 0.f) ? v0 : 0.01f * v0;
            float v1 = acc[i][j][1] + bb1; v1 = (v1 >= 0.f) ? v1 : 0.01f * v1;
            float v2 = acc[i][j][2] + bb0; v2 = (v2 >= 0.f) ? v2 : 0.01f * v2;
            float v3 = acc[i][j][3] + bb1; v3 = (v3 >= 0.f) ? v3 : 0.01f * v3;
            sH[r0 * HS2 + col]           = to_tf32(v0);
            sH[r0 * HS2 + col + 1]       = to_tf32(v1);
            sH[(r0 + 8) * HS2 + col]     = to_tf32(v2);
            sH[(r0 + 8) * HS2 + col + 1] = to_tf32(v3);
        }
    }
}

__global__ void __launch_bounds__(256, 1)
edge_mma_kernel(const float* __restrict__ hV, const float* __restrict__ hE,
                const int* __restrict__ eidx,
                const float* __restrict__ w1, const float* __restrict__ b1,
                const float* __restrict__ w2, const float* __restrict__ b2,
                const float* __restrict__ w3, const float* __restrict__ b3,
                int E)
{
    extern __shared__ float sm[];
    float* s_ac   = sm + SM_AC;
    float* s_w    = sm + SM_W;
    float* s_h1   = sm + SM_H1;
    float* s_h2   = sm + SM_H2;
    float* s_coef = sm + SM_COEF;
    int*   s_dst  = (int*)(sm + SM_DST);

    const int t = threadIdx.x;
    const int e0 = blockIdx.x * 128;
    const int w = t >> 5, lane = t & 31;
    const int lx = lane & 3, ly = lane >> 2;
    const int m0 = (w & 3) * 32, n0 = (w >> 2) * 64;

    if (t < 128) {
        int e = e0 + t;
        int d = (e < E) ? eidx[e] : 0;
        s_dst[t] = d;
        float c = 0.f;
        if (e < E) c = g_att[e] / (g_denom[d] * 30.0f);
        s_coef[t] = c;
    }
    __syncthreads();

    float acc[2][8][4];

    // ---- layer 1: [128x256] @ w1[256x128], leaky ----
#pragma unroll
    for (int i = 0; i < 2; i++)
#pragma unroll
        for (int j = 0; j < 8; j++)
#pragma unroll
            for (int q = 0; q < 4; q++) acc[i][j][q] = 0.f;
    for (int kc = 0; kc < 4; kc++) {
        __syncthreads();
        stage_msg(s_ac, hV, hE, s_dst, e0, kc, E);
        stage_w(s_w, w1 + (size_t)kc * 64 * 128);
        __syncthreads();
        warp_gemm_chunk(s_ac, AS, s_w, acc, m0, n0, lx, ly);
    }
    epi_act(acc, s_h1, b1, m0, n0, lx, ly);

    // ---- layer 2: h1 @ w2[128x128], leaky ----
#pragma unroll
    for (int i = 0; i < 2; i++)
#pragma unroll
        for (int j = 0; j < 8; j++)
#pragma unroll
            for (int q = 0; q < 4; q++) acc[i][j][q] = 0.f;
    for (int kc = 0; kc < 2; kc++) {
        __syncthreads();
        stage_w(s_w, w2 + (size_t)kc * 64 * 128);
        __syncthreads();
        warp_gemm_chunk(s_h1 + kc * 64, HS2, s_w, acc, m0, n0, lx, ly);
    }
    epi_act(acc, s_h2, b2, m0, n0, lx, ly);

    // ---- layer 3: h2 @ w3[128x128] -> scaled atomic scatter ----
#pragma unroll
    for (int i = 0; i < 2; i++)
#pragma unroll
        for (int j = 0; j < 8; j++)
#pragma unroll
            for (int q = 0; q < 4; q++) acc[i][j][q] = 0.f;
    for (int kc = 0; kc < 2; kc++) {
        __syncthreads();
        stage_w(s_w, w3 + (size_t)kc * 64 * 128);
        __syncthreads();
        warp_gemm_chunk(s_h2 + kc * 64, HS2, s_w, acc, m0, n0, lx, ly);
    }
#pragma unroll
    for (int j = 0; j < 8; j++) {
        int col = n0 + 8 * j + 2 * lx;
        float bb0 = __ldg(b3 + col), bb1 = __ldg(b3 + col + 1);
#pragma unroll
        for (int i = 0; i < 2; i++) {
            int r0 = m0 + 16 * i + ly;
#pragma unroll
            for (int half = 0; half < 2; half++) {
                int r = r0 + 8 * half;
                if (e0 + r < E) {
                    float c = s_coef[r];
                    float* dhp = g_dh + (size_t)s_dst[r] * H + col;
                    atomicAdd(dhp,     (acc[i][j][2 * half]     + bb0) * c);
                    atomicAdd(dhp + 1, (acc[i][j][2 * half + 1] + bb1) * c);
                }
            }
        }
    }
}

// ---------------------------------------------------------------------------
// node kernel: 32 nodes/block, 256 threads. LN1 -> FFN(128->512->128) -> LN2
// ---------------------------------------------------------------------------
constexpr int NT = 32;
constexpr int XS = 132;
constexpr int NODE_SMEM = (NT * XS * 2 + 64 * 128) * 4;

__device__ __forceinline__ void ln_rows(float* s, const float* __restrict__ gain,
                                        const float* __restrict__ bias) {
    int t = threadIdx.x;
    int r = t >> 3, p = t & 7;
    float sm = 0.f, sq = 0.f;
#pragma unroll
    for (int c = p; c < H; c += 8) {
        float v = s[r * XS + c];
        sm += v; sq += v * v;
    }
#pragma unroll
    for (int o = 1; o < 8; o <<= 1) {
        sm += __shfl_xor_sync(0xffffffffu, sm, o);
        sq += __shfl_xor_sync(0xffffffffu, sq, o);
    }
    float mu  = sm * (1.f / 128.f);
    float var = sq * (1.f / 128.f) - mu * mu;
    float rs  = rsqrtf(var + 1e-6f);
#pragma unroll
    for (int c = p; c < H; c += 8) {
        float v = s[r * XS + c];
        s[r * XS + c] = gain[c] * (v - mu) * rs + bias[c];
    }
}

__global__ void __launch_bounds__(256)
node_kernel(const float* __restrict__ hV,
            const float* __restrict__ wi, const float* __restrict__ bi,
            const float* __restrict__ wo, const float* __restrict__ bo,
            const float* __restrict__ g1, const float* __restrict__ be1,
            const float* __restrict__ g2, const float* __restrict__ be2,
            float* __restrict__ out, int N)
{
    extern __shared__ float sm[];
    float* s_x  = sm;
    float* s_t  = sm + NT * XS;
    float* s_ws = s_t + NT * XS;

    const int t = threadIdx.x;
    const int n0 = blockIdx.x * NT;

#pragma unroll
    for (int j = 0; j < 16; j++) {
        int idx = t + 256 * j;
        int r = idx >> 7, c = idx & 127;
        int n = n0 + r;
        float v = 0.f;
        if (n < N) v = hV[(size_t)n * H + c] + g_dh[(size_t)n * H + c];
        s_x[r * XS + c] = v;
    }
    __syncthreads();
    ln_rows(s_x, g1, be1);
    __syncthreads();

    const int tx = t & 15, ty = t >> 4;
    float oacc[2][8];
#pragma unroll
    for (int i = 0; i < 2; i++)
#pragma unroll
        for (int j = 0; j < 8; j++) oacc[i][j] = 0.f;

    for (int ch = 0; ch < 4; ch++) {
        float tacc[2][8];
#pragma unroll
        for (int i = 0; i < 2; i++)
#pragma unroll
            for (int j = 0; j < 8; j++) tacc[i][j] = 0.f;
        for (int k0 = 0; k0 < 128; k0 += 64) {
#pragma unroll
            for (int j = 0; j < 8; j++) {
                int idx = t + 256 * j;
                int row = idx >> 5, c4 = idx & 31;
                float4 v = *reinterpret_cast<const float4*>(
                    wi + (size_t)(k0 + row) * 512 + ch * 128 + c4 * 4);
                *reinterpret_cast<float4*>(s_ws + row * 128 + c4 * 4) = v;
            }
            __syncthreads();
#pragma unroll 16
            for (int kk = 0; kk < 64; kk++) {
                float a0 = s_x[(ty * 2 + 0) * XS + k0 + kk];
                float a1 = s_x[(ty * 2 + 1) * XS + k0 + kk];
                float4 wa = *reinterpret_cast<const float4*>(s_ws + kk * 128 + tx * 4);
                float4 wb = *reinterpret_cast<const float4*>(s_ws + kk * 128 + 64 + tx * 4);
                tacc[0][0] += a0 * wa.x; tacc[0][1] += a0 * wa.y; tacc[0][2] += a0 * wa.z; tacc[0][3] += a0 * wa.w;
                tacc[0][4] += a0 * wb.x; tacc[0][5] += a0 * wb.y; tacc[0][6] += a0 * wb.z; tacc[0][7] += a0 * wb.w;
                tacc[1][0] += a1 * wa.x; tacc[1][1] += a1 * wa.y; tacc[1][2] += a1 * wa.z; tacc[1][3] += a1 * wa.w;
                tacc[1][4] += a1 * wb.x; tacc[1][5] += a1 * wb.y; tacc[1][6] += a1 * wb.z; tacc[1][7] += a1 * wb.w;
            }
            __syncthreads();
        }
#pragma unroll
        for (int i = 0; i < 2; i++) {
            int r = ty * 2 + i;
#pragma unroll
            for (int j = 0; j < 8; j++) {
                int col = (j < 4) ? (tx * 4 + j) : (64 + tx * 4 + (j - 4));
                float v = tacc[i][j] + bi[ch * 128 + col];
                s_t[r * XS + col] = fmaxf(v, 0.f);
            }
        }
        for (int k0 = 0; k0 < 128; k0 += 64) {
#pragma unroll
            for (int j = 0; j < 8; j++) {
                int idx = t + 256 * j;
                int row = idx >> 5, c4 = idx & 31;
                float4 v = *reinterpret_cast<const float4*>(
                    wo + (size_t)(ch * 128 + k0 + row) * 128 + c4 * 4);
                *reinterpret_cast<float4*>(s_ws + row * 128 + c4 * 4) = v;
            }
            __syncthreads();
#pragma unroll 16
            for (int kk = 0; kk < 64; kk++) {
                float a0 = s_t[(ty * 2 + 0) * XS + k0 + kk];
                float a1 = s_t[(ty * 2 + 1) * XS + k0 + kk];
                float4 wa = *reinterpret_cast<const float4*>(s_ws + kk * 128 + tx * 4);
                float4 wb = *reinterpret_cast<const float4*>(s_ws + kk * 128 + 64 + tx * 4);
                oacc[0][0] += a0 * wa.x; oacc[0][1] += a0 * wa.y; oacc[0][2] += a0 * wa.z; oacc[0][3] += a0 * wa.w;
                oacc[0][4] += a0 * wb.x; oacc[0][5] += a0 * wb.y; oacc[0][6] += a0 * wb.z; oacc[0][7] += a0 * wb.w;
                oacc[1][0] += a1 * wa.x; oacc[1][1] += a1 * wa.y; oacc[1][2] += a1 * wa.z; oacc[1][3] += a1 * wa.w;
                oacc[1][4] += a1 * wb.x; oacc[1][5] += a1 * wb.y; oacc[1][6] += a1 * wb.z; oacc[1][7] += a1 * wb.w;
            }
            __syncthreads();
        }
    }
#pragma unroll
    for (int i = 0; i < 2; i++) {
        int r = ty * 2 + i;
#pragma unroll
        for (int j = 0; j < 8; j++) {
            int col = (j < 4) ? (tx * 4 + j) : (64 + tx * 4 + (j - 4));
            s_t[r * XS + col] = s_x[r * XS + col] + oacc[i][j] + bo[col];
        }
    }
    __syncthreads();
    ln_rows(s_t, g2, be2);
    __syncthreads();

#pragma unroll
    for (int j = 0; j < 16; j++) {
        int idx = t + 256 * j;
        int r = idx >> 7, c = idx & 127;
        int n = n0 + r;
        if (n < N) out[(size_t)n * H + c] = s_t[r * XS + c];
    }
}

// ---------------------------------------------------------------------------
extern "C" void kernel_launch(void* const* d_in, const int* in_sizes, int n_in,
                              void* d_out, int out_size)
{
    const float* hV  = (const float*)d_in[0];
    const float* hE  = (const float*)d_in[1];
    const float* w1  = (const float*)d_in[2];
    const float* b1  = (const float*)d_in[3];
    const float* w2  = (const float*)d_in[4];
    const float* b2  = (const float*)d_in[5];
    const float* w3  = (const float*)d_in[6];
    const float* b3  = (const float*)d_in[7];
    const float* A   = (const float*)d_in[8];
    const float* wi  = (const float*)d_in[9];
    const float* bi  = (const float*)d_in[10];
    const float* wo  = (const float*)d_in[11];
    const float* bo  = (const float*)d_in[12];
    const float* g1  = (const float*)d_in[13];
    const float* be1 = (const float*)d_in[14];
    const float* g2  = (const float*)d_in[15];
    const float* be2 = (const float*)d_in[16];
    const int*   eix = (const int*)d_in[17];

    int N = in_sizes[0] / H;
    int E = in_sizes[17] / 2;
    float* out = (float*)d_out;

    cudaFuncSetAttribute(edge_mma_kernel, cudaFuncAttributeMaxDynamicSharedMemorySize, EDGE_SMEM);
    cudaFuncSetAttribute(node_kernel, cudaFuncAttributeMaxDynamicSharedMemorySize, NODE_SMEM);

    zero_kernel<<<(N * H + 255) / 256, 256>>>(N);
    att_node_kernel<<<(N + 7) / 8, 256>>>(hV, A, N);
    att_edge_kernel<<<(E + 7) / 8, 256>>>(hE, A, eix, E);
    edge_mma_kernel<<<(E + 127) / 128, 256, EDGE_SMEM>>>(hV, hE, eix, w1, b1, w2, b2, w3, b3, E);
    node_kernel<<<(N + NT - 1) / NT, 256, NODE_SMEM>>>(hV, wi, bi, wo, bo, g1, be1, g2, be2, out, N);
}

// round 4
// speedup vs baseline: 3.4731x; 1.5093x over previous
#include <cuda_runtime.h>
#include <math.h>
#include <stdint.h>

#define H 128
#define MAXE 480000
#define MAXN 20000

// ---- scratch (no allocations allowed) ----
__device__ float g_att[MAXE];
__device__ float g_denom[MAXN];
__device__ float g_p[MAXN];
__device__ float g_dh[(size_t)MAXN * H];

// ---------------------------------------------------------------------------
__device__ __forceinline__ float to_tf32(float x) {
    uint32_t u;
    asm("cvt.rna.tf32.f32 %0, %1;" : "=r"(u) : "f"(x));
    return __uint_as_float(u);
}
__device__ __forceinline__ void mma_tf32(float d[4], const uint32_t a[4],
                                         uint32_t b0, uint32_t b1) {
    asm volatile(
        "mma.sync.aligned.m16n8k8.row.col.f32.tf32.tf32.f32 "
        "{%0,%1,%2,%3}, {%4,%5,%6,%7}, {%8,%9}, {%0,%1,%2,%3};"
        : "+f"(d[0]), "+f"(d[1]), "+f"(d[2]), "+f"(d[3])
        : "r"(a[0]), "r"(a[1]), "r"(a[2]), "r"(a[3]), "r"(b0), "r"(b1));
}

// ---------------------------------------------------------------------------
__global__ void zero_kernel(int N) {
    int i = blockIdx.x * blockDim.x + threadIdx.x;
    if (i < N * H) g_dh[i] = 0.f;
    if (i < N) g_denom[i] = 0.f;
}

__global__ void att_node_kernel(const float* __restrict__ hV,
                                const float* __restrict__ A, int N) {
    int w = (blockIdx.x * blockDim.x + threadIdx.x) >> 5;
    int lane = threadIdx.x & 31;
    if (w >= N) return;
    float4 v = *reinterpret_cast<const float4*>(hV + (size_t)w * H + lane * 4);
    float4 a = *reinterpret_cast<const float4*>(A + lane * 4);
    float s = v.x * a.x + v.y * a.y + v.z * a.z + v.w * a.w;
#pragma unroll
    for (int o = 16; o > 0; o >>= 1) s += __shfl_xor_sync(0xffffffffu, s, o);
    if (lane == 0) g_p[w] = s;
}

__global__ void att_edge_kernel(const float* __restrict__ hE,
                                const float* __restrict__ A,
                                const int* __restrict__ eidx, int E) {
    int w = (blockIdx.x * blockDim.x + threadIdx.x) >> 5;
    int lane = threadIdx.x & 31;
    if (w >= E) return;
    float4 v = *reinterpret_cast<const float4*>(hE + (size_t)w * H + lane * 4);
    float4 a = *reinterpret_cast<const float4*>(A + 128 + lane * 4);
    float s = v.x * a.x + v.y * a.y + v.z * a.z + v.w * a.w;
#pragma unroll
    for (int o = 16; o > 0; o >>= 1) s += __shfl_xor_sync(0xffffffffu, s, o);
    if (lane == 0) {
        int d = eidx[w];
        s += g_p[d];
        float lr = (s >= 0.f) ? s : 0.01f * s;
        float sg = 1.f / (1.f + expf(-lr));
        float att = expf(sg);
        g_att[w] = att;
        atomicAdd(&g_denom[d], att);
    }
}

// ---------------------------------------------------------------------------
// shared tf32 warp-GEMM: one K=64 chunk, warp tile 32x32 (2m x 4n of m16n8k8)
// A: sA[row][lda] row-major fp32(tf32), B: sW[k][136] (k-major)
// ---------------------------------------------------------------------------
__device__ __forceinline__ void wg_tf32(const float* sA, int lda, int aoff,
                                        const float* sW, float acc[2][4][4],
                                        int m0, int n0, int lx, int ly) {
#pragma unroll
    for (int kk = 0; kk < 8; kk++) {
        int kb = kk * 8;
        uint32_t a[2][4];
#pragma unroll
        for (int i = 0; i < 2; i++) {
            const float* ap = sA + (m0 + 16 * i + ly) * lda + aoff + kb + lx;
            a[i][0] = __float_as_uint(ap[0]);
            a[i][1] = __float_as_uint(ap[8 * lda]);
            a[i][2] = __float_as_uint(ap[4]);
            a[i][3] = __float_as_uint(ap[8 * lda + 4]);
        }
#pragma unroll
        for (int j = 0; j < 4; j++) {
            const float* bp = sW + (kb + lx) * 136 + n0 + 8 * j + ly;
            uint32_t b0 = __float_as_uint(bp[0]);
            uint32_t b1 = __float_as_uint(bp[4 * 136]);
#pragma unroll
            for (int i = 0; i < 2; i++) mma_tf32(acc[i][j], a[i], b0, b1);
        }
    }
}

// ---------------------------------------------------------------------------
// edge kernel: 64 edges/CTA, 256 threads (8 warps = 2m x 4n), tf32 MMA
// smem floats: s_a 64x68 | s_w 64x136 | s_h 64x132 | coef 64 | dst 64
// ---------------------------------------------------------------------------
constexpr int TE = 64;
constexpr int OFF_W    = TE * 68;             // 4352
constexpr int OFF_H    = OFF_W + 64 * 136;    // 13056
constexpr int OFF_COEF = OFF_H + TE * 132;    // 21504
constexpr int OFF_DST  = OFF_COEF + TE;       // 21568
constexpr int EDGE_SMEM = (OFF_DST + TE) * 4; // 86528 B

__device__ __forceinline__ void edge_stage_w(float* s_w, const float* __restrict__ Wg,
                                             int kc) {
    int t = threadIdx.x;
#pragma unroll
    for (int jj = 0; jj < 8; jj++) {
        int idx = t + 256 * jj;               // 2048 float4
        int k = idx >> 5, q = idx & 31;
        float4 v = *reinterpret_cast<const float4*>(Wg + (size_t)(kc * 64 + k) * 128 + q * 4);
        v.x = to_tf32(v.x); v.y = to_tf32(v.y); v.z = to_tf32(v.z); v.w = to_tf32(v.w);
        *reinterpret_cast<float4*>(s_w + k * 136 + q * 4) = v;
    }
}

__device__ __forceinline__ void edge_epi(float acc[2][4][4], float* s_h,
                                         const float* __restrict__ bias,
                                         int m0, int n0, int lx, int ly) {
#pragma unroll
    for (int j = 0; j < 4; j++) {
        int col = n0 + 8 * j + 2 * lx;
        float bb0 = __ldg(bias + col), bb1 = __ldg(bias + col + 1);
#pragma unroll
        for (int i = 0; i < 2; i++) {
            int r = m0 + 16 * i + ly;
            float v0 = acc[i][j][0] + bb0; v0 = (v0 >= 0.f) ? v0 : 0.01f * v0;
            float v1 = acc[i][j][1] + bb1; v1 = (v1 >= 0.f) ? v1 : 0.01f * v1;
            float v2 = acc[i][j][2] + bb0; v2 = (v2 >= 0.f) ? v2 : 0.01f * v2;
            float v3 = acc[i][j][3] + bb1; v3 = (v3 >= 0.f) ? v3 : 0.01f * v3;
            s_h[r * 132 + col]           = to_tf32(v0);
            s_h[r * 132 + col + 1]       = to_tf32(v1);
            s_h[(r + 8) * 132 + col]     = to_tf32(v2);
            s_h[(r + 8) * 132 + col + 1] = to_tf32(v3);
        }
    }
}

__global__ void __launch_bounds__(256, 2)
edge_mma_kernel(const float* __restrict__ hV, const float* __restrict__ hE,
                const int* __restrict__ eidx,
                const float* __restrict__ w1, const float* __restrict__ b1,
                const float* __restrict__ w2, const float* __restrict__ b2,
                const float* __restrict__ w3, const float* __restrict__ b3,
                int E)
{
    extern __shared__ float sm[];
    float* s_a    = sm;
    float* s_w    = sm + OFF_W;
    float* s_h    = sm + OFF_H;
    float* s_coef = sm + OFF_COEF;
    int*   s_dst  = (int*)(sm + OFF_DST);

    const int t = threadIdx.x;
    const int e0 = blockIdx.x * TE;
    const int w = t >> 5, lane = t & 31;
    const int lx = lane & 3, ly = lane >> 2;
    const int m0 = (w & 1) * 32, n0 = (w >> 1) * 32;

    if (t < TE) {
        int e = e0 + t;
        s_dst[t]  = (e < E) ? eidx[e] : 0;
        s_coef[t] = (e < E) ? g_att[e] : 0.f;
    }
    __syncthreads();

    float acc[2][4][4];
#pragma unroll
    for (int i = 0; i < 2; i++)
#pragma unroll
        for (int j = 0; j < 4; j++)
#pragma unroll
            for (int q = 0; q < 4; q++) acc[i][j][q] = 0.f;

    // ---- layer 1: msg[64x256] @ w1, K in 4 chunks of 64 ----
    for (int kc = 0; kc < 4; kc++) {
        // stage A chunk (cols kc*64..+63): hV gather for kc<2, hE for kc>=2
#pragma unroll
        for (int jj = 0; jj < 4; jj++) {
            int idx = t + 256 * jj;           // 1024 float4
            int r = idx >> 4, q = idx & 15;
            float4 v = make_float4(0.f, 0.f, 0.f, 0.f);
            int e = e0 + r;
            if (e < E) {
                if (kc < 2)
                    v = *reinterpret_cast<const float4*>(
                        hV + (size_t)s_dst[r] * H + kc * 64 + q * 4);
                else
                    v = *reinterpret_cast<const float4*>(
                        hE + (size_t)e * H + (kc - 2) * 64 + q * 4);
            }
            v.x = to_tf32(v.x); v.y = to_tf32(v.y);
            v.z = to_tf32(v.z); v.w = to_tf32(v.w);
            *reinterpret_cast<float4*>(s_a + r * 68 + q * 4) = v;
        }
        edge_stage_w(s_w, w1, kc);
        __syncthreads();
        wg_tf32(s_a, 68, 0, s_w, acc, m0, n0, lx, ly);
        __syncthreads();
    }
    edge_epi(acc, s_h, b1, m0, n0, lx, ly);

    // ---- layer 2: h1 @ w2 ----
#pragma unroll
    for (int i = 0; i < 2; i++)
#pragma unroll
        for (int j = 0; j < 4; j++)
#pragma unroll
            for (int q = 0; q < 4; q++) acc[i][j][q] = 0.f;
    for (int kc = 0; kc < 2; kc++) {
        edge_stage_w(s_w, w2, kc);
        __syncthreads();                     // also makes epi(h1) visible
        wg_tf32(s_h, 132, kc * 64, s_w, acc, m0, n0, lx, ly);
        __syncthreads();
    }
    edge_epi(acc, s_h, b2, m0, n0, lx, ly);  // h2 in place (post-sync safe)

    // ---- layer 3: h2 @ w3 -> scaled float2 atomics ----
#pragma unroll
    for (int i = 0; i < 2; i++)
#pragma unroll
        for (int j = 0; j < 4; j++)
#pragma unroll
            for (int q = 0; q < 4; q++) acc[i][j][q] = 0.f;
    for (int kc = 0; kc < 2; kc++) {
        edge_stage_w(s_w, w3, kc);
        __syncthreads();
        wg_tf32(s_h, 132, kc * 64, s_w, acc, m0, n0, lx, ly);
        __syncthreads();
    }
#pragma unroll
    for (int j = 0; j < 4; j++) {
        int col = n0 + 8 * j + 2 * lx;
        float bb0 = __ldg(b3 + col), bb1 = __ldg(b3 + col + 1);
#pragma unroll
        for (int i = 0; i < 2; i++) {
            int r = m0 + 16 * i + ly;
            if (e0 + r < E) {
                float c = s_coef[r];
                float2 v = make_float2((acc[i][j][0] + bb0) * c,
                                       (acc[i][j][1] + bb1) * c);
                atomicAdd(reinterpret_cast<float2*>(
                              &g_dh[(size_t)s_dst[r] * H + col]), v);
            }
            int r8 = r + 8;
            if (e0 + r8 < E) {
                float c = s_coef[r8];
                float2 v = make_float2((acc[i][j][2] + bb0) * c,
                                       (acc[i][j][3] + bb1) * c);
                atomicAdd(reinterpret_cast<float2*>(
                              &g_dh[(size_t)s_dst[r8] * H + col]), v);
            }
        }
    }
}

// ---------------------------------------------------------------------------
// node tf32 MMA kernel: 64 nodes/CTA, 256 threads (8 warps, 2m x 4n of 32x32)
// smem fp32: s_x 64x132 | s_hm 64x132 | s_w 64x136
// ---------------------------------------------------------------------------
constexpr int NODE_SMEM = (64 * 132 * 2 + 64 * 136) * 4;

template <bool ROUND>
__device__ __forceinline__ void ln64(float* s, const float* __restrict__ gain,
                                     const float* __restrict__ bias) {
    int t = threadIdx.x;
    int r = t >> 2, p = t & 3;
    float* row = s + r * 132;
    float sm = 0.f, sq = 0.f;
#pragma unroll
    for (int c = p; c < 128; c += 4) {
        float v = row[c];
        sm += v; sq += v * v;
    }
    sm += __shfl_xor_sync(0xffffffffu, sm, 1);
    sq += __shfl_xor_sync(0xffffffffu, sq, 1);
    sm += __shfl_xor_sync(0xffffffffu, sm, 2);
    sq += __shfl_xor_sync(0xffffffffu, sq, 2);
    float mu  = sm * (1.f / 128.f);
    float var = sq * (1.f / 128.f) - mu * mu;
    float rs  = rsqrtf(var + 1e-6f);
#pragma unroll
    for (int c = p; c < 128; c += 4) {
        float v = gain[c] * (row[c] - mu) * rs + bias[c];
        row[c] = ROUND ? to_tf32(v) : v;
    }
}

__global__ void __launch_bounds__(256, 2)
node_mma_kernel(const float* __restrict__ hV,
                const float* __restrict__ wi, const float* __restrict__ bi,
                const float* __restrict__ wo, const float* __restrict__ bo,
                const float* __restrict__ g1, const float* __restrict__ be1,
                const float* __restrict__ g2, const float* __restrict__ be2,
                float* __restrict__ out, int N)
{
    extern __shared__ float smf[];
    float* s_x  = smf;
    float* s_hm = smf + 64 * 132;
    float* s_w  = smf + 2 * 64 * 132;

    const int t = threadIdx.x;
    const int nb0 = blockIdx.x * 64;
    const int w = t >> 5, lane = t & 31;
    const int lx = lane & 3, ly = lane >> 2;
    const int m0 = (w & 1) * 32, n0 = (w >> 1) * 32;

    // x = hV + dh/(denom*30)
#pragma unroll
    for (int jj = 0; jj < 8; jj++) {
        int idx = t + 256 * jj;
        int r = idx >> 5, c4 = idx & 31;
        int n = nb0 + r;
        float4 x = make_float4(0.f, 0.f, 0.f, 0.f);
        if (n < N) {
            float den = g_denom[n];
            float cf = (den > 0.f) ? 1.f / (den * 30.f) : 0.f;
            float4 h = *reinterpret_cast<const float4*>(hV + (size_t)n * H + c4 * 4);
            float4 d = *reinterpret_cast<const float4*>(g_dh + (size_t)n * H + c4 * 4);
            x = make_float4(h.x + d.x * cf, h.y + d.y * cf,
                            h.z + d.z * cf, h.w + d.w * cf);
        }
        *reinterpret_cast<float4*>(s_x + r * 132 + c4 * 4) = x;
    }
    __syncthreads();
    ln64<true>(s_x, g1, be1);
    __syncthreads();

    float oacc[2][4][4];
#pragma unroll
    for (int i = 0; i < 2; i++)
#pragma unroll
        for (int j = 0; j < 4; j++)
#pragma unroll
            for (int q = 0; q < 4; q++) oacc[i][j][q] = 0.f;

    for (int ch = 0; ch < 4; ch++) {
        float tacc[2][4][4];
#pragma unroll
        for (int i = 0; i < 2; i++)
#pragma unroll
            for (int j = 0; j < 4; j++)
#pragma unroll
                for (int q = 0; q < 4; q++) tacc[i][j][q] = 0.f;
        for (int k0 = 0; k0 < 128; k0 += 64) {
            __syncthreads();
#pragma unroll
            for (int jj = 0; jj < 8; jj++) {
                int idx = t + 256 * jj;
                int k = idx >> 5, c4 = idx & 31;
                float4 v = *reinterpret_cast<const float4*>(
                    wi + (size_t)(k0 + k) * 512 + ch * 128 + c4 * 4);
                v.x = to_tf32(v.x); v.y = to_tf32(v.y);
                v.z = to_tf32(v.z); v.w = to_tf32(v.w);
                *reinterpret_cast<float4*>(s_w + k * 136 + c4 * 4) = v;
            }
            __syncthreads();
            wg_tf32(s_x, 132, k0, s_w, tacc, m0, n0, lx, ly);
        }
        // relu epilogue -> s_hm
#pragma unroll
        for (int j = 0; j < 4; j++) {
            int col = n0 + 8 * j + 2 * lx;
            float bb0 = __ldg(bi + ch * 128 + col), bb1 = __ldg(bi + ch * 128 + col + 1);
#pragma unroll
            for (int i = 0; i < 2; i++) {
                int r = m0 + 16 * i + ly;
                s_hm[r * 132 + col]           = to_tf32(fmaxf(tacc[i][j][0] + bb0, 0.f));
                s_hm[r * 132 + col + 1]       = to_tf32(fmaxf(tacc[i][j][1] + bb1, 0.f));
                s_hm[(r + 8) * 132 + col]     = to_tf32(fmaxf(tacc[i][j][2] + bb0, 0.f));
                s_hm[(r + 8) * 132 + col + 1] = to_tf32(fmaxf(tacc[i][j][3] + bb1, 0.f));
            }
        }
        for (int k0 = 0; k0 < 128; k0 += 64) {
            __syncthreads();
#pragma unroll
            for (int jj = 0; jj < 8; jj++) {
                int idx = t + 256 * jj;
                int k = idx >> 5, c4 = idx & 31;
                float4 v = *reinterpret_cast<const float4*>(
                    wo + (size_t)(ch * 128 + k0 + k) * 128 + c4 * 4);
                v.x = to_tf32(v.x); v.y = to_tf32(v.y);
                v.z = to_tf32(v.z); v.w = to_tf32(v.w);
                *reinterpret_cast<float4*>(s_w + k * 136 + c4 * 4) = v;
            }
            __syncthreads();
            wg_tf32(s_hm, 132, k0, s_w, oacc, m0, n0, lx, ly);
        }
    }
    __syncthreads();
#pragma unroll
    for (int j = 0; j < 4; j++) {
        int col = n0 + 8 * j + 2 * lx;
        float bb0 = __ldg(bo + col), bb1 = __ldg(bo + col + 1);
#pragma unroll
        for (int i = 0; i < 2; i++) {
            int r = m0 + 16 * i + ly;
            s_hm[r * 132 + col]           = s_x[r * 132 + col] + oacc[i][j][0] + bb0;
            s_hm[r * 132 + col + 1]       = s_x[r * 132 + col + 1] + oacc[i][j][1] + bb1;
            s_hm[(r + 8) * 132 + col]     = s_x[(r + 8) * 132 + col] + oacc[i][j][2] + bb0;
            s_hm[(r + 8) * 132 + col + 1] = s_x[(r + 8) * 132 + col + 1] + oacc[i][j][3] + bb1;
        }
    }
    __syncthreads();
    ln64<false>(s_hm, g2, be2);
    __syncthreads();

#pragma unroll
    for (int jj = 0; jj < 8; jj++) {
        int idx = t + 256 * jj;
        int r = idx >> 5, c4 = idx & 31;
        int n = nb0 + r;
        if (n < N)
            *reinterpret_cast<float4*>(out + (size_t)n * H + c4 * 4) =
                *reinterpret_cast<const float4*>(s_hm + r * 132 + c4 * 4);
    }
}

// ---------------------------------------------------------------------------
extern "C" void kernel_launch(void* const* d_in, const int* in_sizes, int n_in,
                              void* d_out, int out_size)
{
    const float* hV  = (const float*)d_in[0];
    const float* hE  = (const float*)d_in[1];
    const float* w1  = (const float*)d_in[2];
    const float* b1  = (const float*)d_in[3];
    const float* w2  = (const float*)d_in[4];
    const float* b2  = (const float*)d_in[5];
    const float* w3  = (const float*)d_in[6];
    const float* b3  = (const float*)d_in[7];
    const float* A   = (const float*)d_in[8];
    const float* wi  = (const float*)d_in[9];
    const float* bi  = (const float*)d_in[10];
    const float* wo  = (const float*)d_in[11];
    const float* bo  = (const float*)d_in[12];
    const float* g1  = (const float*)d_in[13];
    const float* be1 = (const float*)d_in[14];
    const float* g2  = (const float*)d_in[15];
    const float* be2 = (const float*)d_in[16];
    const int*   eix = (const int*)d_in[17];

    int N = in_sizes[0] / H;
    int E = in_sizes[17] / 2;
    float* out = (float*)d_out;

    cudaFuncSetAttribute(edge_mma_kernel, cudaFuncAttributeMaxDynamicSharedMemorySize, EDGE_SMEM);
    cudaFuncSetAttribute(node_mma_kernel, cudaFuncAttributeMaxDynamicSharedMemorySize, NODE_SMEM);

    zero_kernel<<<(N * H + 255) / 256, 256>>>(N);
    att_node_kernel<<<(N + 7) / 8, 256>>>(hV, A, N);
    att_edge_kernel<<<(E + 7) / 8, 256>>>(hE, A, eix, E);
    edge_mma_kernel<<<(E + TE - 1) / TE, 256, EDGE_SMEM>>>(hV, hE, eix,
                                                           w1, b1, w2, b2, w3, b3, E);
    node_mma_kernel<<<(N + 63) / 64, 256, NODE_SMEM>>>(hV, wi, bi, wo, bo,
                                                       g1, be1, g2, be2, out, N);
}

// round 7
// speedup vs baseline: 4.4160x; 1.2715x over previous
#include <cuda_runtime.h>
#include <math.h>
#include <stdint.h>

#define H 128
#define MAXE 480000
#define MAXN 20000

// ---- scratch (no allocations allowed) ----
__device__ float g_att[MAXE];
__device__ float g_denom[MAXN];
__device__ float g_p[MAXN];
__device__ float g_P[(size_t)MAXN * H];      // hV @ W1v + b1 (fp32)
__device__ float g_dh[(size_t)MAXN * H];
__device__ float g_wr[3 * 128 * 128];        // tf32-rounded edge weights [layer][k][n]

// ---------------------------------------------------------------------------
__device__ __forceinline__ float to_tf32(float x) {
    uint32_t u;
    asm("cvt.rna.tf32.f32 %0, %1;" : "=r"(u) : "f"(x));
    return __uint_as_float(u);
}
__device__ __forceinline__ void mma_tf32(float d[4], const uint32_t a[4],
                                         uint32_t b0, uint32_t b1) {
    asm volatile(
        "mma.sync.aligned.m16n8k8.row.col.f32.tf32.tf32.f32 "
        "{%0,%1,%2,%3}, {%4,%5,%6,%7}, {%8,%9}, {%0,%1,%2,%3};"
        : "+f"(d[0]), "+f"(d[1]), "+f"(d[2]), "+f"(d[3])
        : "r"(a[0]), "r"(a[1]), "r"(a[2]), "r"(a[3]), "r"(b0), "r"(b1));
}
#define CP_ASYNC16(dst32, srcp) \
    asm volatile("cp.async.cg.shared.global [%0], [%1], 16;" :: "r"(dst32), "l"(srcp))
#define CP_COMMIT() asm volatile("cp.async.commit_group;" ::: "memory")
#define CP_WAIT1()  asm volatile("cp.async.wait_group 1;" ::: "memory")
#define CP_WAIT0()  asm volatile("cp.async.wait_group 0;" ::: "memory")

// ---------------------------------------------------------------------------
__global__ void zero_kernel(int N) {
    int i = blockIdx.x * blockDim.x + threadIdx.x;
    if (i < N * H) g_dh[i] = 0.f;
    if (i < N) g_denom[i] = 0.f;
}

// pre-round edge-MLP weights to tf32: layer0 = w1[128:256] (hE part), w2, w3
__global__ void prew_kernel(const float* __restrict__ w1,
                            const float* __restrict__ w2,
                            const float* __restrict__ w3) {
    int i = blockIdx.x * blockDim.x + threadIdx.x;
    if (i >= 3 * 128 * 128) return;
    int l = i >> 14, idx = i & 16383;
    const float* src = (l == 0) ? (w1 + 128 * 128 + idx)
                                : ((l == 1) ? (w2 + idx) : (w3 + idx));
    g_wr[i] = to_tf32(*src);
}

__global__ void att_node_kernel(const float* __restrict__ hV,
                                const float* __restrict__ A, int N) {
    int w = (blockIdx.x * blockDim.x + threadIdx.x) >> 5;
    int lane = threadIdx.x & 31;
    if (w >= N) return;
    float4 v = *reinterpret_cast<const float4*>(hV + (size_t)w * H + lane * 4);
    float4 a = *reinterpret_cast<const float4*>(A + lane * 4);
    float s = v.x * a.x + v.y * a.y + v.z * a.z + v.w * a.w;
#pragma unroll
    for (int o = 16; o > 0; o >>= 1) s += __shfl_xor_sync(0xffffffffu, s, o);
    if (lane == 0) g_p[w] = s;
}

__global__ void att_edge_kernel(const float* __restrict__ hE,
                                const float* __restrict__ A,
                                const int* __restrict__ eidx, int E) {
    int w = (blockIdx.x * blockDim.x + threadIdx.x) >> 5;
    int lane = threadIdx.x & 31;
    if (w >= E) return;
    float4 v = *reinterpret_cast<const float4*>(hE + (size_t)w * H + lane * 4);
    float4 a = *reinterpret_cast<const float4*>(A + 128 + lane * 4);
    float s = v.x * a.x + v.y * a.y + v.z * a.z + v.w * a.w;
#pragma unroll
    for (int o = 16; o > 0; o >>= 1) s += __shfl_xor_sync(0xffffffffu, s, o);
    if (lane == 0) {
        int d = eidx[w];
        s += g_p[d];
        float lr = (s >= 0.f) ? s : 0.01f * s;
        float sg = 1.f / (1.f + expf(-lr));
        float att = expf(sg);
        g_att[w] = att;
        atomicAdd(&g_denom[d], att);
    }
}

// ---------------------------------------------------------------------------
// generic warp GEMM chunk (32x32 warp tile): used by p_kernel / node kernel
// ---------------------------------------------------------------------------
__device__ __forceinline__ void wg_tf32(const float* sA, int lda, int aoff,
                                        const float* sW, float acc[2][4][4],
                                        int m0, int n0, int lx, int ly) {
#pragma unroll
    for (int kk = 0; kk < 8; kk++) {
        int kb = kk * 8;
        uint32_t a[2][4];
#pragma unroll
        for (int i = 0; i < 2; i++) {
            const float* ap = sA + (m0 + 16 * i + ly) * lda + aoff + kb + lx;
            a[i][0] = __float_as_uint(ap[0]);
            a[i][1] = __float_as_uint(ap[8 * lda]);
            a[i][2] = __float_as_uint(ap[4]);
            a[i][3] = __float_as_uint(ap[8 * lda + 4]);
        }
#pragma unroll
        for (int j = 0; j < 4; j++) {
            const float* bp = sW + (kb + lx) * 136 + n0 + 8 * j + ly;
            uint32_t b0 = __float_as_uint(bp[0]);
            uint32_t b1 = __float_as_uint(bp[4 * 136]);
#pragma unroll
            for (int i = 0; i < 2; i++) mma_tf32(acc[i][j], a[i], b0, b1);
        }
    }
}

// ---------------------------------------------------------------------------
// p_kernel: P[n] = hV[n] @ w1[0:128] + b1, 64 nodes/CTA, tf32 MMA
// ---------------------------------------------------------------------------
constexpr int P_SMEM = (64 * 132 + 64 * 136) * 4;

__global__ void __launch_bounds__(256, 2)
p_kernel(const float* __restrict__ hV, const float* __restrict__ w1,
         const float* __restrict__ b1, int N)
{
    extern __shared__ float smf[];
    float* s_a = smf;                 // 64 x 132
    float* s_w = smf + 64 * 132;      // 64 x 136

    const int t = threadIdx.x;
    const int nb0 = blockIdx.x * 64;
    const int w = t >> 5, lane = t & 31;
    const int lx = lane & 3, ly = lane >> 2;
    const int m0 = (w & 1) * 32, n0 = (w >> 1) * 32;

#pragma unroll
    for (int jj = 0; jj < 8; jj++) {
        int idx = t + 256 * jj;        // 2048 float4
        int r = idx >> 5, c4 = idx & 31;
        int n = nb0 + r;
        float4 v = make_float4(0.f, 0.f, 0.f, 0.f);
        if (n < N) v = *reinterpret_cast<const float4*>(hV + (size_t)n * H + c4 * 4);
        v.x = to_tf32(v.x); v.y = to_tf32(v.y); v.z = to_tf32(v.z); v.w = to_tf32(v.w);
        *reinterpret_cast<float4*>(s_a + r * 132 + c4 * 4) = v;
    }

    float acc[2][4][4];
#pragma unroll
    for (int i = 0; i < 2; i++)
#pragma unroll
        for (int j = 0; j < 4; j++)
#pragma unroll
            for (int q = 0; q < 4; q++) acc[i][j][q] = 0.f;

    for (int kc = 0; kc < 2; kc++) {
        __syncthreads();
#pragma unroll
        for (int jj = 0; jj < 8; jj++) {
            int idx = t + 256 * jj;
            int k = idx >> 5, c4 = idx & 31;
            float4 v = *reinterpret_cast<const float4*>(
                w1 + (size_t)(kc * 64 + k) * 128 + c4 * 4);
            v.x = to_tf32(v.x); v.y = to_tf32(v.y); v.z = to_tf32(v.z); v.w = to_tf32(v.w);
            *reinterpret_cast<float4*>(s_w + k * 136 + c4 * 4) = v;
        }
        __syncthreads();
        wg_tf32(s_a, 132, kc * 64, s_w, acc, m0, n0, lx, ly);
    }
#pragma unroll
    for (int j = 0; j < 4; j++) {
        int col = n0 + 8 * j + 2 * lx;
        float bb0 = __ldg(b1 + col), bb1 = __ldg(b1 + col + 1);
#pragma unroll
        for (int i = 0; i < 2; i++) {
#pragma unroll
            for (int hf = 0; hf < 2; hf++) {
                int r = m0 + 16 * i + ly + 8 * hf;
                int n = nb0 + r;
                if (n < N) {
                    float2 v = make_float2(acc[i][j][2 * hf] + bb0,
                                           acc[i][j][2 * hf + 1] + bb1);
                    *reinterpret_cast<float2*>(g_P + (size_t)n * H + col) = v;
                }
            }
        }
    }
}

// ---------------------------------------------------------------------------
// edge kernel: 128 edges/CTA, 256 threads (8 warps = 4m x 2n of 32x64 tiles)
// 3 GEMMs of 128x128x128; weights cp.async double-buffered (32-k chunks)
// smem: s_h 128x132 | s_w 2 x 32x136 | coef 128 | dst 128 = 103,424 B
// ---------------------------------------------------------------------------
constexpr int S_H = 0;
constexpr int S_W = 128 * 132;               // 16896
constexpr int S_COEF = S_W + 2 * 32 * 136;   // 25600
constexpr int S_DST = S_COEF + 128;          // 25728
constexpr int EDGE_SMEM = (S_DST + 128) * 4; // 103424

__global__ void __launch_bounds__(256, 2)
edge_mma_kernel(const float* __restrict__ hE, const int* __restrict__ eidx,
                const float* __restrict__ b2, const float* __restrict__ b3, int E)
{
    extern __shared__ float sm[];
    float* s_h    = sm + S_H;
    float* s_coef = sm + S_COEF;
    int*   s_dst  = (int*)(sm + S_DST);
    const uint32_t sb = (uint32_t)__cvta_generic_to_shared(sm);

    const int t = threadIdx.x;
    const int e0 = blockIdx.x * 128;
    const int w = t >> 5, lane = t & 31;
    const int lx = lane & 3, ly = lane >> 2;
    const int m0 = (w & 3) * 32, n0 = (w >> 2) * 64;

    if (t < 128) {
        int e = e0 + t;
        s_dst[t]  = (e < E) ? eidx[e] : 0;
        s_coef[t] = (e < E) ? g_att[e] : 0.f;
    }

    // stage hE tile -> s_h (rna tf32)
#pragma unroll
    for (int jj = 0; jj < 16; jj++) {
        int idx = t + 256 * jj;               // 4096 float4
        int r = idx >> 5, c4 = idx & 31;
        float4 v = make_float4(0.f, 0.f, 0.f, 0.f);
        if (e0 + r < E)
            v = *reinterpret_cast<const float4*>(hE + (size_t)(e0 + r) * H + c4 * 4);
        v.x = to_tf32(v.x); v.y = to_tf32(v.y); v.z = to_tf32(v.z); v.w = to_tf32(v.w);
        *reinterpret_cast<float4*>(s_h + r * 132 + c4 * 4) = v;
    }

    // prologue: async-copy weight chunks 0 and 1
#pragma unroll
    for (int c = 0; c < 2; c++) {
        const float* src = g_wr + (c & 3) * 32 * 128;   // layer 0
        uint32_t dstb = sb + (S_W + (c & 1) * 32 * 136) * 4;
#pragma unroll
        for (int jj = 0; jj < 4; jj++) {
            int o = t + 256 * jj;             // 1024 x 16B
            int row = o >> 5, c4 = o & 31;
            CP_ASYNC16(dstb + (row * 136 + c4 * 4) * 4, src + row * 128 + c4 * 4);
        }
        CP_COMMIT();
    }

    float acc[2][8][4];
#pragma unroll
    for (int i = 0; i < 2; i++)
#pragma unroll
        for (int j = 0; j < 8; j++)
#pragma unroll
            for (int q = 0; q < 4; q++) acc[i][j][q] = 0.f;

    for (int c = 0; c < 12; c++) {
        if (c < 11) CP_WAIT1(); else CP_WAIT0();
        __syncthreads();

        // MMA on chunk c: A cols (c&3)*32 .. +31, weights in buf c&1
        {
            const int ac0 = (c & 3) * 32;
            const float* bw = sm + S_W + (c & 1) * 32 * 136;
#pragma unroll
            for (int kk = 0; kk < 4; kk++) {
                int kb = kk * 8;
                uint32_t a[2][4];
#pragma unroll
                for (int i = 0; i < 2; i++) {
                    const float* ap = s_h + (m0 + 16 * i + ly) * 132 + ac0 + kb + lx;
                    a[i][0] = __float_as_uint(ap[0]);
                    a[i][1] = __float_as_uint(ap[8 * 132]);
                    a[i][2] = __float_as_uint(ap[4]);
                    a[i][3] = __float_as_uint(ap[8 * 132 + 4]);
                }
#pragma unroll
                for (int j = 0; j < 8; j++) {
                    const float* bp = bw + (kb + lx) * 136 + n0 + 8 * j + ly;
                    uint32_t b0 = __float_as_uint(bp[0]);
                    uint32_t b1 = __float_as_uint(bp[4 * 136]);
#pragma unroll
                    for (int i = 0; i < 2; i++) mma_tf32(acc[i][j], a[i], b0, b1);
                }
            }
        }
        __syncthreads();

        if (c < 10) {   // async-copy chunk c+2 into the buffer just freed
            int cn = c + 2;
            const float* src = g_wr + (cn >> 2) * 16384 + (cn & 3) * 32 * 128;
            uint32_t dstb = sb + (S_W + (cn & 1) * 32 * 136) * 4;
#pragma unroll
            for (int jj = 0; jj < 4; jj++) {
                int o = t + 256 * jj;
                int row = o >> 5, c4 = o & 31;
                CP_ASYNC16(dstb + (row * 136 + c4 * 4) * 4, src + row * 128 + c4 * 4);
            }
            CP_COMMIT();
        }

        if (c == 3) {
            // epilogue 1: h1 = leaky(acc + P[dst]) -> s_h (rna)
#pragma unroll
            for (int j = 0; j < 8; j++) {
                int col = n0 + 8 * j + 2 * lx;
#pragma unroll
                for (int i = 0; i < 2; i++) {
#pragma unroll
                    for (int hf = 0; hf < 2; hf++) {
                        int r = m0 + 16 * i + ly + 8 * hf;
                        float2 p = *reinterpret_cast<const float2*>(
                            g_P + (size_t)s_dst[r] * H + col);
                        float v0 = acc[i][j][2 * hf]     + p.x;
                        float v1 = acc[i][j][2 * hf + 1] + p.y;
                        v0 = (v0 >= 0.f) ? v0 : 0.01f * v0;
                        v1 = (v1 >= 0.f) ? v1 : 0.01f * v1;
                        float2 o2 = make_float2(to_tf32(v0), to_tf32(v1));
                        *reinterpret_cast<float2*>(s_h + r * 132 + col) = o2;
                        acc[i][j][2 * hf] = 0.f; acc[i][j][2 * hf + 1] = 0.f;
                    }
                }
            }
        } else if (c == 7) {
            // epilogue 2: h2 = leaky(acc + b2) -> s_h (rna)
#pragma unroll
            for (int j = 0; j < 8; j++) {
                int col = n0 + 8 * j + 2 * lx;
                float bb0 = __ldg(b2 + col), bb1 = __ldg(b2 + col + 1);
#pragma unroll
                for (int i = 0; i < 2; i++) {
#pragma unroll
                    for (int hf = 0; hf < 2; hf++) {
                        int r = m0 + 16 * i + ly + 8 * hf;
                        float v0 = acc[i][j][2 * hf]     + bb0;
                        float v1 = acc[i][j][2 * hf + 1] + bb1;
                        v0 = (v0 >= 0.f) ? v0 : 0.01f * v0;
                        v1 = (v1 >= 0.f) ? v1 : 0.01f * v1;
                        float2 o2 = make_float2(to_tf32(v0), to_tf32(v1));
                        *reinterpret_cast<float2*>(s_h + r * 132 + col) = o2;
                        acc[i][j][2 * hf] = 0.f; acc[i][j][2 * hf + 1] = 0.f;
                    }
                }
            }
        }
    }

    // final epilogue: (acc + b3) * att -> float2 atomics into g_dh
#pragma unroll
    for (int j = 0; j < 8; j++) {
        int col = n0 + 8 * j + 2 * lx;
        float bb0 = __ldg(b3 + col), bb1 = __ldg(b3 + col + 1);
#pragma unroll
        for (int i = 0; i < 2; i++) {
#pragma unroll
            for (int hf = 0; hf < 2; hf++) {
                int r = m0 + 16 * i + ly + 8 * hf;
                if (e0 + r < E) {
                    float cf = s_coef[r];
                    float2 v = make_float2((acc[i][j][2 * hf]     + bb0) * cf,
                                           (acc[i][j][2 * hf + 1] + bb1) * cf);
                    atomicAdd(reinterpret_cast<float2*>(
                                  &g_dh[(size_t)s_dst[r] * H + col]), v);
                }
            }
        }
    }
}

// ---------------------------------------------------------------------------
// node tf32 MMA kernel (round-4 version, unchanged)
// ---------------------------------------------------------------------------
constexpr int NODE_SMEM = (64 * 132 * 2 + 64 * 136) * 4;

template <bool ROUND>
__device__ __forceinline__ void ln64(float* s, const float* __restrict__ gain,
                                     const float* __restrict__ bias) {
    int t = threadIdx.x;
    int r = t >> 2, p = t & 3;
    float* row = s + r * 132;
    float sm = 0.f, sq = 0.f;
#pragma unroll
    for (int c = p; c < 128; c += 4) {
        float v = row[c];
        sm += v; sq += v * v;
    }
    sm += __shfl_xor_sync(0xffffffffu, sm, 1);
    sq += __shfl_xor_sync(0xffffffffu, sq, 1);
    sm += __shfl_xor_sync(0xffffffffu, sm, 2);
    sq += __shfl_xor_sync(0xffffffffu, sq, 2);
    float mu  = sm * (1.f / 128.f);
    float var = sq * (1.f / 128.f) - mu * mu;
    float rs  = rsqrtf(var + 1e-6f);
#pragma unroll
    for (int c = p; c < 128; c += 4) {
        float v = gain[c] * (row[c] - mu) * rs + bias[c];
        row[c] = ROUND ? to_tf32(v) : v;
    }
}

__global__ void __launch_bounds__(256, 2)
node_mma_kernel(const float* __restrict__ hV,
                const float* __restrict__ wi, const float* __restrict__ bi,
                const float* __restrict__ wo, const float* __restrict__ bo,
                const float* __restrict__ g1, const float* __restrict__ be1,
                const float* __restrict__ g2, const float* __restrict__ be2,
                float* __restrict__ out, int N)
{
    extern __shared__ float smf[];
    float* s_x  = smf;
    float* s_hm = smf + 64 * 132;
    float* s_w  = smf + 2 * 64 * 132;

    const int t = threadIdx.x;
    const int nb0 = blockIdx.x * 64;
    const int w = t >> 5, lane = t & 31;
    const int lx = lane & 3, ly = lane >> 2;
    const int m0 = (w & 1) * 32, n0 = (w >> 1) * 32;

#pragma unroll
    for (int jj = 0; jj < 8; jj++) {
        int idx = t + 256 * jj;
        int r = idx >> 5, c4 = idx & 31;
        int n = nb0 + r;
        float4 x = make_float4(0.f, 0.f, 0.f, 0.f);
        if (n < N) {
            float den = g_denom[n];
            float cf = (den > 0.f) ? 1.f / (den * 30.f) : 0.f;
            float4 h = *reinterpret_cast<const float4*>(hV + (size_t)n * H + c4 * 4);
            float4 d = *reinterpret_cast<const float4*>(g_dh + (size_t)n * H + c4 * 4);
            x = make_float4(h.x + d.x * cf, h.y + d.y * cf,
                            h.z + d.z * cf, h.w + d.w * cf);
        }
        *reinterpret_cast<float4*>(s_x + r * 132 + c4 * 4) = x;
    }
    __syncthreads();
    ln64<true>(s_x, g1, be1);
    __syncthreads();

    float oacc[2][4][4];
#pragma unroll
    for (int i = 0; i < 2; i++)
#pragma unroll
        for (int j = 0; j < 4; j++)
#pragma unroll
            for (int q = 0; q < 4; q++) oacc[i][j][q] = 0.f;

    for (int ch = 0; ch < 4; ch++) {
        float tacc[2][4][4];
#pragma unroll
        for (int i = 0; i < 2; i++)
#pragma unroll
            for (int j = 0; j < 4; j++)
#pragma unroll
                for (int q = 0; q < 4; q++) tacc[i][j][q] = 0.f;
        for (int k0 = 0; k0 < 128; k0 += 64) {
            __syncthreads();
#pragma unroll
            for (int jj = 0; jj < 8; jj++) {
                int idx = t + 256 * jj;
                int k = idx >> 5, c4 = idx & 31;
                float4 v = *reinterpret_cast<const float4*>(
                    wi + (size_t)(k0 + k) * 512 + ch * 128 + c4 * 4);
                v.x = to_tf32(v.x); v.y = to_tf32(v.y);
                v.z = to_tf32(v.z); v.w = to_tf32(v.w);
                *reinterpret_cast<float4*>(s_w + k * 136 + c4 * 4) = v;
            }
            __syncthreads();
            wg_tf32(s_x, 132, k0, s_w, tacc, m0, n0, lx, ly);
        }
#pragma unroll
        for (int j = 0; j < 4; j++) {
            int col = n0 + 8 * j + 2 * lx;
            float bb0 = __ldg(bi + ch * 128 + col), bb1 = __ldg(bi + ch * 128 + col + 1);
#pragma unroll
            for (int i = 0; i < 2; i++) {
                int r = m0 + 16 * i + ly;
                s_hm[r * 132 + col]           = to_tf32(fmaxf(tacc[i][j][0] + bb0, 0.f));
                s_hm[r * 132 + col + 1]       = to_tf32(fmaxf(tacc[i][j][1] + bb1, 0.f));
                s_hm[(r + 8) * 132 + col]     = to_tf32(fmaxf(tacc[i][j][2] + bb0, 0.f));
                s_hm[(r + 8) * 132 + col + 1] = to_tf32(fmaxf(tacc[i][j][3] + bb1, 0.f));
            }
        }
        for (int k0 = 0; k0 < 128; k0 += 64) {
            __syncthreads();
#pragma unroll
            for (int jj = 0; jj < 8; jj++) {
                int idx = t + 256 * jj;
                int k = idx >> 5, c4 = idx & 31;
                float4 v = *reinterpret_cast<const float4*>(
                    wo + (size_t)(ch * 128 + k0 + k) * 128 + c4 * 4);
                v.x = to_tf32(v.x); v.y = to_tf32(v.y);
                v.z = to_tf32(v.z); v.w = to_tf32(v.w);
                *reinterpret_cast<float4*>(s_w + k * 136 + c4 * 4) = v;
            }
            __syncthreads();
            wg_tf32(s_hm, 132, k0, s_w, oacc, m0, n0, lx, ly);
        }
    }
    __syncthreads();
#pragma unroll
    for (int j = 0; j < 4; j++) {
        int col = n0 + 8 * j + 2 * lx;
        float bb0 = __ldg(bo + col), bb1 = __ldg(bo + col + 1);
#pragma unroll
        for (int i = 0; i < 2; i++) {
            int r = m0 + 16 * i + ly;
            s_hm[r * 132 + col]           = s_x[r * 132 + col] + oacc[i][j][0] + bb0;
            s_hm[r * 132 + col + 1]       = s_x[r * 132 + col + 1] + oacc[i][j][1] + bb1;
            s_hm[(r + 8) * 132 + col]     = s_x[(r + 8) * 132 + col] + oacc[i][j][2] + bb0;
            s_hm[(r + 8) * 132 + col + 1] = s_x[(r + 8) * 132 + col + 1] + oacc[i][j][3] + bb1;
        }
    }
    __syncthreads();
    ln64<false>(s_hm, g2, be2);
    __syncthreads();

#pragma unroll
    for (int jj = 0; jj < 8; jj++) {
        int idx = t + 256 * jj;
        int r = idx >> 5, c4 = idx & 31;
        int n = nb0 + r;
        if (n < N)
            *reinterpret_cast<float4*>(out + (size_t)n * H + c4 * 4) =
                *reinterpret_cast<const float4*>(s_hm + r * 132 + c4 * 4);
    }
}

// ---------------------------------------------------------------------------
extern "C" void kernel_launch(void* const* d_in, const int* in_sizes, int n_in,
                              void* d_out, int out_size)
{
    const float* hV  = (const float*)d_in[0];
    const float* hE  = (const float*)d_in[1];
    const float* w1  = (const float*)d_in[2];
    const float* b1  = (const float*)d_in[3];
    const float* w2  = (const float*)d_in[4];
    const float* b2  = (const float*)d_in[5];
    const float* w3  = (const float*)d_in[6];
    const float* b3  = (const float*)d_in[7];
    const float* A   = (const float*)d_in[8];
    const float* wi  = (const float*)d_in[9];
    const float* bi  = (const float*)d_in[10];
    const float* wo  = (const float*)d_in[11];
    const float* bo  = (const float*)d_in[12];
    const float* g1  = (const float*)d_in[13];
    const float* be1 = (const float*)d_in[14];
    const float* g2  = (const float*)d_in[15];
    const float* be2 = (const float*)d_in[16];
    const int*   eix = (const int*)d_in[17];

    int N = in_sizes[0] / H;
    int E = in_sizes[17] / 2;
    float* out = (float*)d_out;

    cudaFuncSetAttribute(edge_mma_kernel, cudaFuncAttributeMaxDynamicSharedMemorySize, EDGE_SMEM);
    cudaFuncSetAttribute(node_mma_kernel, cudaFuncAttributeMaxDynamicSharedMemorySize, NODE_SMEM);
    cudaFuncSetAttribute(p_kernel, cudaFuncAttributeMaxDynamicSharedMemorySize, P_SMEM);

    zero_kernel<<<(N * H + 255) / 256, 256>>>(N);
    prew_kernel<<<192, 256>>>(w1, w2, w3);
    att_node_kernel<<<(N + 7) / 8, 256>>>(hV, A, N);
    att_edge_kernel<<<(E + 7) / 8, 256>>>(hE, A, eix, E);
    p_kernel<<<(N + 63) / 64, 256, P_SMEM>>>(hV, w1, b1, N);
    edge_mma_kernel<<<(E + 127) / 128, 256, EDGE_SMEM>>>(hE, eix, b2, b3, E);
    node_mma_kernel<<<(N + 63) / 64, 256, NODE_SMEM>>>(hV, wi, bi, wo, bo,
                                                       g1, be1, g2, be2, out, N);
}

// round 8
// speedup vs baseline: 4.4744x; 1.0132x over previous
#include <cuda_runtime.h>
#include <math.h>
#include <stdint.h>

#define H 128
#define MAXE 480000
#define MAXN 20000

// ---- scratch (no allocations allowed) ----
__device__ float g_denom[MAXN];
__device__ float g_p[MAXN];
__device__ float g_P[(size_t)MAXN * H];      // hV @ W1v + b1 (fp32)
__device__ float g_dh[(size_t)MAXN * H];
__device__ float g_wr[3 * 128 * 128];        // tf32-rounded edge weights [layer][k][n]

// ---------------------------------------------------------------------------
__device__ __forceinline__ float to_tf32(float x) {
    uint32_t u;
    asm("cvt.rna.tf32.f32 %0, %1;" : "=r"(u) : "f"(x));
    return __uint_as_float(u);
}
__device__ __forceinline__ void mma_tf32(float d[4], const uint32_t a[4],
                                         uint32_t b0, uint32_t b1) {
    asm volatile(
        "mma.sync.aligned.m16n8k8.row.col.f32.tf32.tf32.f32 "
        "{%0,%1,%2,%3}, {%4,%5,%6,%7}, {%8,%9}, {%0,%1,%2,%3};"
        : "+f"(d[0]), "+f"(d[1]), "+f"(d[2]), "+f"(d[3])
        : "r"(a[0]), "r"(a[1]), "r"(a[2]), "r"(a[3]), "r"(b0), "r"(b1));
}
#define CP_ASYNC16(dst32, srcp) \
    asm volatile("cp.async.cg.shared.global [%0], [%1], 16;" :: "r"(dst32), "l"(srcp))
#define CP_COMMIT() asm volatile("cp.async.commit_group;" ::: "memory")
#define CP_WAIT1()  asm volatile("cp.async.wait_group 1;" ::: "memory")
#define CP_WAIT0()  asm volatile("cp.async.wait_group 0;" ::: "memory")

// ---------------------------------------------------------------------------
__global__ void zero_kernel(int N) {
    int i = blockIdx.x * blockDim.x + threadIdx.x;
    if (i < N * H) g_dh[i] = 0.f;
    if (i < N) g_denom[i] = 0.f;
}

// pre-round edge-MLP weights to tf32: layer0 = w1[128:256] (hE part), w2, w3
__global__ void prew_kernel(const float* __restrict__ w1,
                            const float* __restrict__ w2,
                            const float* __restrict__ w3) {
    int i = blockIdx.x * blockDim.x + threadIdx.x;
    if (i >= 3 * 128 * 128) return;
    int l = i >> 14, idx = i & 16383;
    const float* src = (l == 0) ? (w1 + 128 * 128 + idx)
                                : ((l == 1) ? (w2 + idx) : (w3 + idx));
    g_wr[i] = to_tf32(*src);
}

// ---------------------------------------------------------------------------
// generic warp GEMM chunk (32x32 warp tile)
// ---------------------------------------------------------------------------
__device__ __forceinline__ void wg_tf32(const float* sA, int lda, int aoff,
                                        const float* sW, float acc[2][4][4],
                                        int m0, int n0, int lx, int ly) {
#pragma unroll
    for (int kk = 0; kk < 8; kk++) {
        int kb = kk * 8;
        uint32_t a[2][4];
#pragma unroll
        for (int i = 0; i < 2; i++) {
            const float* ap = sA + (m0 + 16 * i + ly) * lda + aoff + kb + lx;
            a[i][0] = __float_as_uint(ap[0]);
            a[i][1] = __float_as_uint(ap[8 * lda]);
            a[i][2] = __float_as_uint(ap[4]);
            a[i][3] = __float_as_uint(ap[8 * lda + 4]);
        }
#pragma unroll
        for (int j = 0; j < 4; j++) {
            const float* bp = sW + (kb + lx) * 136 + n0 + 8 * j + ly;
            uint32_t b0 = __float_as_uint(bp[0]);
            uint32_t b1 = __float_as_uint(bp[4 * 136]);
#pragma unroll
            for (int i = 0; i < 2; i++) mma_tf32(acc[i][j], a[i], b0, b1);
        }
    }
}

// ---------------------------------------------------------------------------
// p_kernel: P[n] = hV[n] @ w1[0:128] + b1 ; g_p[n] = hV[n] . A[0:128]
// 64 nodes/CTA, 256 threads, tf32 MMA
// ---------------------------------------------------------------------------
constexpr int P_SMEM = (64 * 132 + 64 * 136) * 4;

__global__ void __launch_bounds__(256, 2)
p_kernel(const float* __restrict__ hV, const float* __restrict__ w1,
         const float* __restrict__ b1, const float* __restrict__ A, int N)
{
    extern __shared__ float smf[];
    float* s_a = smf;                 // 64 x 132
    float* s_w = smf + 64 * 132;      // 64 x 136

    const int t = threadIdx.x;
    const int nb0 = blockIdx.x * 64;
    const int w = t >> 5, lane = t & 31;
    const int lx = lane & 3, ly = lane >> 2;
    const int m0 = (w & 1) * 32, n0 = (w >> 1) * 32;

#pragma unroll
    for (int jj = 0; jj < 8; jj++) {
        int idx = t + 256 * jj;        // 2048 float4
        int r = idx >> 5, c4 = idx & 31;
        int n = nb0 + r;
        float4 v = make_float4(0.f, 0.f, 0.f, 0.f);
        if (n < N) v = *reinterpret_cast<const float4*>(hV + (size_t)n * H + c4 * 4);
        v.x = to_tf32(v.x); v.y = to_tf32(v.y); v.z = to_tf32(v.z); v.w = to_tf32(v.w);
        *reinterpret_cast<float4*>(s_a + r * 132 + c4 * 4) = v;
    }

    // fused att_node: g_p[n] = dot(hV[n], A[0:128]) in fp32 (hV is L1-hot)
    {
        int r = t >> 2, p3 = t & 3;
        int n = nb0 + r;
        if (n < N) {
            float s = 0.f;
#pragma unroll
            for (int q = 0; q < 8; q++) {
                float4 v = *reinterpret_cast<const float4*>(hV + (size_t)n * H + p3 * 32 + q * 4);
                float4 a = *reinterpret_cast<const float4*>(A + p3 * 32 + q * 4);
                s += v.x * a.x + v.y * a.y + v.z * a.z + v.w * a.w;
            }
            s += __shfl_xor_sync(0xffffffffu, s, 1);
            s += __shfl_xor_sync(0xffffffffu, s, 2);
            if (p3 == 0) g_p[n] = s;
        }
    }

    float acc[2][4][4];
#pragma unroll
    for (int i = 0; i < 2; i++)
#pragma unroll
        for (int j = 0; j < 4; j++)
#pragma unroll
            for (int q = 0; q < 4; q++) acc[i][j][q] = 0.f;

    for (int kc = 0; kc < 2; kc++) {
        __syncthreads();
#pragma unroll
        for (int jj = 0; jj < 8; jj++) {
            int idx = t + 256 * jj;
            int k = idx >> 5, c4 = idx & 31;
            float4 v = *reinterpret_cast<const float4*>(
                w1 + (size_t)(kc * 64 + k) * 128 + c4 * 4);
            v.x = to_tf32(v.x); v.y = to_tf32(v.y); v.z = to_tf32(v.z); v.w = to_tf32(v.w);
            *reinterpret_cast<float4*>(s_w + k * 136 + c4 * 4) = v;
        }
        __syncthreads();
        wg_tf32(s_a, 132, kc * 64, s_w, acc, m0, n0, lx, ly);
    }
#pragma unroll
    for (int j = 0; j < 4; j++) {
        int col = n0 + 8 * j + 2 * lx;
        float bb0 = __ldg(b1 + col), bb1 = __ldg(b1 + col + 1);
#pragma unroll
        for (int i = 0; i < 2; i++) {
#pragma unroll
            for (int hf = 0; hf < 2; hf++) {
                int r = m0 + 16 * i + ly + 8 * hf;
                int n = nb0 + r;
                if (n < N) {
                    float2 v = make_float2(acc[i][j][2 * hf] + bb0,
                                           acc[i][j][2 * hf + 1] + bb1);
                    *reinterpret_cast<float2*>(g_P + (size_t)n * H + col) = v;
                }
            }
        }
    }
}

// ---------------------------------------------------------------------------
// edge kernel: 128 edges/CTA, 256 threads (8 warps = 4m x 2n of 32x64 tiles)
// fused attention (att + denom atomics) + 3 GEMMs + scatter
// smem: s_h 128x132 | s_w 2 x 32x136 | coef 128 | dst 128 = 103,424 B
// ---------------------------------------------------------------------------
constexpr int S_H = 0;
constexpr int S_W = 128 * 132;               // 16896
constexpr int S_COEF = S_W + 2 * 32 * 136;   // 25600
constexpr int S_DST = S_COEF + 128;          // 25728
constexpr int EDGE_SMEM = (S_DST + 128) * 4; // 103424

__global__ void __launch_bounds__(256, 2)
edge_mma_kernel(const float* __restrict__ hE, const int* __restrict__ eidx,
                const float* __restrict__ A,
                const float* __restrict__ b2, const float* __restrict__ b3, int E)
{
    extern __shared__ float sm[];
    float* s_h    = sm + S_H;
    float* s_coef = sm + S_COEF;
    int*   s_dst  = (int*)(sm + S_DST);
    const uint32_t sb = (uint32_t)__cvta_generic_to_shared(sm);

    const int t = threadIdx.x;
    const int e0 = blockIdx.x * 128;
    const int w = t >> 5, lane = t & 31;
    const int lx = lane & 3, ly = lane >> 2;
    const int m0 = (w & 3) * 32, n0 = (w >> 2) * 64;

    if (t < 128) {
        int e = e0 + t;
        s_dst[t] = (e < E) ? eidx[e] : 0;
    }

    // stage hE tile -> s_h (rna tf32)
#pragma unroll
    for (int jj = 0; jj < 16; jj++) {
        int idx = t + 256 * jj;               // 4096 float4
        int r = idx >> 5, c4 = idx & 31;
        float4 v = make_float4(0.f, 0.f, 0.f, 0.f);
        if (e0 + r < E)
            v = *reinterpret_cast<const float4*>(hE + (size_t)(e0 + r) * H + c4 * 4);
        v.x = to_tf32(v.x); v.y = to_tf32(v.y); v.z = to_tf32(v.z); v.w = to_tf32(v.w);
        *reinterpret_cast<float4*>(s_h + r * 132 + c4 * 4) = v;
    }

    // prologue: async-copy weight chunks 0 and 1
#pragma unroll
    for (int c = 0; c < 2; c++) {
        const float* src = g_wr + (c & 3) * 32 * 128;   // layer 0
        uint32_t dstb = sb + (S_W + (c & 1) * 32 * 136) * 4;
#pragma unroll
        for (int jj = 0; jj < 4; jj++) {
            int o = t + 256 * jj;             // 1024 x 16B
            int row = o >> 5, c4 = o & 31;
            CP_ASYNC16(dstb + (row * 136 + c4 * 4) * 4, src + row * 128 + c4 * 4);
        }
        CP_COMMIT();
    }
    __syncthreads();                          // s_dst visible to all

    // fused att_edge: 2 threads/edge, fp32 dot over hE (L1-hot) + g_p[dst]
    {
        int r = t >> 1, ph = t & 1;
        int e = e0 + r;
        if (e < E) {
            float s = 0.f;
            const float* he = hE + (size_t)e * H + ph * 64;
            const float* av = A + 128 + ph * 64;
#pragma unroll
            for (int q = 0; q < 16; q++) {
                float4 v = *reinterpret_cast<const float4*>(he + q * 4);
                float4 a = *reinterpret_cast<const float4*>(av + q * 4);
                s += v.x * a.x + v.y * a.y + v.z * a.z + v.w * a.w;
            }
            s += __shfl_xor_sync(0xffffffffu, s, 1);
            if (ph == 0) {
                int d = s_dst[r];
                s += g_p[d];
                float lr = (s >= 0.f) ? s : 0.01f * s;
                float sg = 1.f / (1.f + expf(-lr));
                float att = expf(sg);
                s_coef[r] = att;
                atomicAdd(&g_denom[d], att);
            }
        } else if (ph == 0) {
            s_coef[r] = 0.f;
        }
    }

    float acc[2][8][4];
#pragma unroll
    for (int i = 0; i < 2; i++)
#pragma unroll
        for (int j = 0; j < 8; j++)
#pragma unroll
            for (int q = 0; q < 4; q++) acc[i][j][q] = 0.f;

    for (int c = 0; c < 12; c++) {
        if (c < 11) CP_WAIT1(); else CP_WAIT0();
        __syncthreads();

        // MMA on chunk c: A cols (c&3)*32 .. +31, weights in buf c&1
        {
            const int ac0 = (c & 3) * 32;
            const float* bw = sm + S_W + (c & 1) * 32 * 136;
#pragma unroll
            for (int kk = 0; kk < 4; kk++) {
                int kb = kk * 8;
                uint32_t a[2][4];
#pragma unroll
                for (int i = 0; i < 2; i++) {
                    const float* ap = s_h + (m0 + 16 * i + ly) * 132 + ac0 + kb + lx;
                    a[i][0] = __float_as_uint(ap[0]);
                    a[i][1] = __float_as_uint(ap[8 * 132]);
                    a[i][2] = __float_as_uint(ap[4]);
                    a[i][3] = __float_as_uint(ap[8 * 132 + 4]);
                }
#pragma unroll
                for (int j = 0; j < 8; j++) {
                    const float* bp = bw + (kb + lx) * 136 + n0 + 8 * j + ly;
                    uint32_t b0 = __float_as_uint(bp[0]);
                    uint32_t b1 = __float_as_uint(bp[4 * 136]);
#pragma unroll
                    for (int i = 0; i < 2; i++) mma_tf32(acc[i][j], a[i], b0, b1);
                }
            }
        }
        __syncthreads();

        if (c < 10) {   // async-copy chunk c+2 into the buffer just freed
            int cn = c + 2;
            const float* src = g_wr + (cn >> 2) * 16384 + (cn & 3) * 32 * 128;
            uint32_t dstb = sb + (S_W + (cn & 1) * 32 * 136) * 4;
#pragma unroll
            for (int jj = 0; jj < 4; jj++) {
                int o = t + 256 * jj;
                int row = o >> 5, c4 = o & 31;
                CP_ASYNC16(dstb + (row * 136 + c4 * 4) * 4, src + row * 128 + c4 * 4);
            }
            CP_COMMIT();
        }

        if (c == 3) {
            // epilogue 1: h1 = leaky(acc + P[dst]) -> s_h (rna)
#pragma unroll
            for (int j = 0; j < 8; j++) {
                int col = n0 + 8 * j + 2 * lx;
#pragma unroll
                for (int i = 0; i < 2; i++) {
#pragma unroll
                    for (int hf = 0; hf < 2; hf++) {
                        int r = m0 + 16 * i + ly + 8 * hf;
                        float2 p = *reinterpret_cast<const float2*>(
                            g_P + (size_t)s_dst[r] * H + col);
                        float v0 = acc[i][j][2 * hf]     + p.x;
                        float v1 = acc[i][j][2 * hf + 1] + p.y;
                        v0 = (v0 >= 0.f) ? v0 : 0.01f * v0;
                        v1 = (v1 >= 0.f) ? v1 : 0.01f * v1;
                        float2 o2 = make_float2(to_tf32(v0), to_tf32(v1));
                        *reinterpret_cast<float2*>(s_h + r * 132 + col) = o2;
                        acc[i][j][2 * hf] = 0.f; acc[i][j][2 * hf + 1] = 0.f;
                    }
                }
            }
        } else if (c == 7) {
            // epilogue 2: h2 = leaky(acc + b2) -> s_h (rna)
#pragma unroll
            for (int j = 0; j < 8; j++) {
                int col = n0 + 8 * j + 2 * lx;
                float bb0 = __ldg(b2 + col), bb1 = __ldg(b2 + col + 1);
#pragma unroll
                for (int i = 0; i < 2; i++) {
#pragma unroll
                    for (int hf = 0; hf < 2; hf++) {
                        int r = m0 + 16 * i + ly + 8 * hf;
                        float v0 = acc[i][j][2 * hf]     + bb0;
                        float v1 = acc[i][j][2 * hf + 1] + bb1;
                        v0 = (v0 >= 0.f) ? v0 : 0.01f * v0;
                        v1 = (v1 >= 0.f) ? v1 : 0.01f * v1;
                        float2 o2 = make_float2(to_tf32(v0), to_tf32(v1));
                        *reinterpret_cast<float2*>(s_h + r * 132 + col) = o2;
                        acc[i][j][2 * hf] = 0.f; acc[i][j][2 * hf + 1] = 0.f;
                    }
                }
            }
        }
    }

    // final epilogue: (acc + b3) * att -> float2 atomics into g_dh
#pragma unroll
    for (int j = 0; j < 8; j++) {
        int col = n0 + 8 * j + 2 * lx;
        float bb0 = __ldg(b3 + col), bb1 = __ldg(b3 + col + 1);
#pragma unroll
        for (int i = 0; i < 2; i++) {
#pragma unroll
            for (int hf = 0; hf < 2; hf++) {
                int r = m0 + 16 * i + ly + 8 * hf;
                if (e0 + r < E) {
                    float cf = s_coef[r];
                    float2 v = make_float2((acc[i][j][2 * hf]     + bb0) * cf,
                                           (acc[i][j][2 * hf + 1] + bb1) * cf);
                    atomicAdd(reinterpret_cast<float2*>(
                                  &g_dh[(size_t)s_dst[r] * H + col]), v);
                }
            }
        }
    }
}

// ---------------------------------------------------------------------------
// node tf32 MMA kernel (unchanged)
// ---------------------------------------------------------------------------
constexpr int NODE_SMEM = (64 * 132 * 2 + 64 * 136) * 4;

template <bool ROUND>
__device__ __forceinline__ void ln64(float* s, const float* __restrict__ gain,
                                     const float* __restrict__ bias) {
    int t = threadIdx.x;
    int r = t >> 2, p = t & 3;
    float* row = s + r * 132;
    float sm = 0.f, sq = 0.f;
#pragma unroll
    for (int c = p; c < 128; c += 4) {
        float v = row[c];
        sm += v; sq += v * v;
    }
    sm += __shfl_xor_sync(0xffffffffu, sm, 1);
    sq += __shfl_xor_sync(0xffffffffu, sq, 1);
    sm += __shfl_xor_sync(0xffffffffu, sm, 2);
    sq += __shfl_xor_sync(0xffffffffu, sq, 2);
    float mu  = sm * (1.f / 128.f);
    float var = sq * (1.f / 128.f) - mu * mu;
    float rs  = rsqrtf(var + 1e-6f);
#pragma unroll
    for (int c = p; c < 128; c += 4) {
        float v = gain[c] * (row[c] - mu) * rs + bias[c];
        row[c] = ROUND ? to_tf32(v) : v;
    }
}

__global__ void __launch_bounds__(256, 2)
node_mma_kernel(const float* __restrict__ hV,
                const float* __restrict__ wi, const float* __restrict__ bi,
                const float* __restrict__ wo, const float* __restrict__ bo,
                const float* __restrict__ g1, const float* __restrict__ be1,
                const float* __restrict__ g2, const float* __restrict__ be2,
                float* __restrict__ out, int N)
{
    extern __shared__ float smf[];
    float* s_x  = smf;
    float* s_hm = smf + 64 * 132;
    float* s_w  = smf + 2 * 64 * 132;

    const int t = threadIdx.x;
    const int nb0 = blockIdx.x * 64;
    const int w = t >> 5, lane = t & 31;
    const int lx = lane & 3, ly = lane >> 2;
    const int m0 = (w & 1) * 32, n0 = (w >> 1) * 32;

#pragma unroll
    for (int jj = 0; jj < 8; jj++) {
        int idx = t + 256 * jj;
        int r = idx >> 5, c4 = idx & 31;
        int n = nb0 + r;
        float4 x = make_float4(0.f, 0.f, 0.f, 0.f);
        if (n < N) {
            float den = g_denom[n];
            float cf = (den > 0.f) ? 1.f / (den * 30.f) : 0.f;
            float4 h = *reinterpret_cast<const float4*>(hV + (size_t)n * H + c4 * 4);
            float4 d = *reinterpret_cast<const float4*>(g_dh + (size_t)n * H + c4 * 4);
            x = make_float4(h.x + d.x * cf, h.y + d.y * cf,
                            h.z + d.z * cf, h.w + d.w * cf);
        }
        *reinterpret_cast<float4*>(s_x + r * 132 + c4 * 4) = x;
    }
    __syncthreads();
    ln64<true>(s_x, g1, be1);
    __syncthreads();

    float oacc[2][4][4];
#pragma unroll
    for (int i = 0; i < 2; i++)
#pragma unroll
        for (int j = 0; j < 4; j++)
#pragma unroll
            for (int q = 0; q < 4; q++) oacc[i][j][q] = 0.f;

    for (int ch = 0; ch < 4; ch++) {
        float tacc[2][4][4];
#pragma unroll
        for (int i = 0; i < 2; i++)
#pragma unroll
            for (int j = 0; j < 4; j++)
#pragma unroll
                for (int q = 0; q < 4; q++) tacc[i][j][q] = 0.f;
        for (int k0 = 0; k0 < 128; k0 += 64) {
            __syncthreads();
#pragma unroll
            for (int jj = 0; jj < 8; jj++) {
                int idx = t + 256 * jj;
                int k = idx >> 5, c4 = idx & 31;
                float4 v = *reinterpret_cast<const float4*>(
                    wi + (size_t)(k0 + k) * 512 + ch * 128 + c4 * 4);
                v.x = to_tf32(v.x); v.y = to_tf32(v.y);
                v.z = to_tf32(v.z); v.w = to_tf32(v.w);
                *reinterpret_cast<float4*>(s_w + k * 136 + c4 * 4) = v;
            }
            __syncthreads();
            wg_tf32(s_x, 132, k0, s_w, tacc, m0, n0, lx, ly);
        }
#pragma unroll
        for (int j = 0; j < 4; j++) {
            int col = n0 + 8 * j + 2 * lx;
            float bb0 = __ldg(bi + ch * 128 + col), bb1 = __ldg(bi + ch * 128 + col + 1);
#pragma unroll
            for (int i = 0; i < 2; i++) {
                int r = m0 + 16 * i + ly;
                s_hm[r * 132 + col]           = to_tf32(fmaxf(tacc[i][j][0] + bb0, 0.f));
                s_hm[r * 132 + col + 1]       = to_tf32(fmaxf(tacc[i][j][1] + bb1, 0.f));
                s_hm[(r + 8) * 132 + col]     = to_tf32(fmaxf(tacc[i][j][2] + bb0, 0.f));
                s_hm[(r + 8) * 132 + col + 1] = to_tf32(fmaxf(tacc[i][j][3] + bb1, 0.f));
            }
        }
        for (int k0 = 0; k0 < 128; k0 += 64) {
            __syncthreads();
#pragma unroll
            for (int jj = 0; jj < 8; jj++) {
                int idx = t + 256 * jj;
                int k = idx >> 5, c4 = idx & 31;
                float4 v = *reinterpret_cast<const float4*>(
                    wo + (size_t)(ch * 128 + k0 + k) * 128 + c4 * 4);
                v.x = to_tf32(v.x); v.y = to_tf32(v.y);
                v.z = to_tf32(v.z); v.w = to_tf32(v.w);
                *reinterpret_cast<float4*>(s_w + k * 136 + c4 * 4) = v;
            }
            __syncthreads();
            wg_tf32(s_hm, 132, k0, s_w, oacc, m0, n0, lx, ly);
        }
    }
    __syncthreads();
#pragma unroll
    for (int j = 0; j < 4; j++) {
        int col = n0 + 8 * j + 2 * lx;
        float bb0 = __ldg(bo + col), bb1 = __ldg(bo + col + 1);
#pragma unroll
        for (int i = 0; i < 2; i++) {
            int r = m0 + 16 * i + ly;
            s_hm[r * 132 + col]           = s_x[r * 132 + col] + oacc[i][j][0] + bb0;
            s_hm[r * 132 + col + 1]       = s_x[r * 132 + col + 1] + oacc[i][j][1] + bb1;
            s_hm[(r + 8) * 132 + col]     = s_x[(r + 8) * 132 + col] + oacc[i][j][2] + bb0;
            s_hm[(r + 8) * 132 + col + 1] = s_x[(r + 8) * 132 + col + 1] + oacc[i][j][3] + bb1;
        }
    }
    __syncthreads();
    ln64<false>(s_hm, g2, be2);
    __syncthreads();

#pragma unroll
    for (int jj = 0; jj < 8; jj++) {
        int idx = t + 256 * jj;
        int r = idx >> 5, c4 = idx & 31;
        int n = nb0 + r;
        if (n < N)
            *reinterpret_cast<float4*>(out + (size_t)n * H + c4 * 4) =
                *reinterpret_cast<const float4*>(s_hm + r * 132 + c4 * 4);
    }
}

// ---------------------------------------------------------------------------
extern "C" void kernel_launch(void* const* d_in, const int* in_sizes, int n_in,
                              void* d_out, int out_size)
{
    const float* hV  = (const float*)d_in[0];
    const float* hE  = (const float*)d_in[1];
    const float* w1  = (const float*)d_in[2];
    const float* b1  = (const float*)d_in[3];
    const float* w2  = (const float*)d_in[4];
    const float* b2  = (const float*)d_in[5];
    const float* w3  = (const float*)d_in[6];
    const float* b3  = (const float*)d_in[7];
    const float* A   = (const float*)d_in[8];
    const float* wi  = (const float*)d_in[9];
    const float* bi  = (const float*)d_in[10];
    const float* wo  = (const float*)d_in[11];
    const float* bo  = (const float*)d_in[12];
    const float* g1  = (const float*)d_in[13];
    const float* be1 = (const float*)d_in[14];
    const float* g2  = (const float*)d_in[15];
    const float* be2 = (const float*)d_in[16];
    const int*   eix = (const int*)d_in[17];

    int N = in_sizes[0] / H;
    int E = in_sizes[17] / 2;
    float* out = (float*)d_out;

    cudaFuncSetAttribute(edge_mma_kernel, cudaFuncAttributeMaxDynamicSharedMemorySize, EDGE_SMEM);
    cudaFuncSetAttribute(node_mma_kernel, cudaFuncAttributeMaxDynamicSharedMemorySize, NODE_SMEM);
    cudaFuncSetAttribute(p_kernel, cudaFuncAttributeMaxDynamicSharedMemorySize, P_SMEM);

    zero_kernel<<<(N * H + 255) / 256, 256>>>(N);
    prew_kernel<<<192, 256>>>(w1, w2, w3);
    p_kernel<<<(N + 63) / 64, 256, P_SMEM>>>(hV, w1, b1, A, N);
    edge_mma_kernel<<<(E + 127) / 128, 256, EDGE_SMEM>>>(hE, eix, A, b2, b3, E);
    node_mma_kernel<<<(N + 63) / 64, 256, NODE_SMEM>>>(hV, wi, bi, wo, bo,
                                                       g1, be1, g2, be2, out, N);
}